// round 4
// baseline (speedup 1.0000x reference)
#include <cuda_runtime.h>
#include <cstdint>
#include <cstddef>

// Problem constants
#define B_    2
#define S_    2048
#define D_    1024
#define H_    16
#define DK_   64
#define MTOT  4096        // B_*S_
#define HB_   32          // H_*B_

// ---------------------------------------------------------------------------
// Scratch (static device allocations; no dynamic alloc allowed)
// ---------------------------------------------------------------------------
static __device__ float g_qx[B_ * H_ * S_ * DK_];   // [b][h][s][dk]
static __device__ float g_kx[B_ * H_ * S_ * DK_];
static __device__ float g_vx[B_ * H_ * S_ * DK_];
static __device__ float g_ctx[(size_t)MTOT * D_];   // [b*S+s][h*64+dk]
static __device__ float g_dense[(size_t)MTOT * D_];
static __device__ float g_rinv[HB_ * S_];           // 1/rowsum per attn row

// ---------------------------------------------------------------------------
// Helpers
// ---------------------------------------------------------------------------
__device__ __forceinline__ float tf32_hi(float x) {
    uint32_t r;
    asm("cvt.rna.tf32.f32 %0, %1;" : "=r"(r) : "f"(x));
    return __uint_as_float(r);
}

__device__ __forceinline__ void mma_tf32(float c[4],
                                         uint32_t a0, uint32_t a1, uint32_t a2, uint32_t a3,
                                         uint32_t b0, uint32_t b1) {
    asm volatile(
        "mma.sync.aligned.m16n8k8.row.col.f32.tf32.tf32.f32 "
        "{%0,%1,%2,%3}, {%4,%5,%6,%7}, {%8,%9}, {%0,%1,%2,%3};\n"
        : "+f"(c[0]), "+f"(c[1]), "+f"(c[2]), "+f"(c[3])
        : "r"(a0), "r"(a1), "r"(a2), "r"(a3), "r"(b0), "r"(b1));
}

// ---------------------------------------------------------------------------
// Generic 3xTF32 GEMM:  C[4096 x 1024] = A[4096 x 1024] @ W[1024 x 1024]^T + bias
// mode 0/1/2 : scatter into g_qx/g_kx/g_vx as [b][h][s][dk]
// mode 3     : A = g_ctx (arg ignored), out = relu(C) into g_dense row-major
// BM=128 BN=128 BK=16, 256 threads, warps 2(m) x 4(n), warp tile 64x32
// ---------------------------------------------------------------------------
__global__ __launch_bounds__(256) void proj_gemm(const float* __restrict__ A,
                                                 const float* __restrict__ W,
                                                 const float* __restrict__ bias,
                                                 int mode) {
    __shared__ float As_h[128 * 20];
    __shared__ float As_l[128 * 20];
    __shared__ float Bs_h[128 * 20];
    __shared__ float Bs_l[128 * 20];

    const float* Ap = (mode == 3) ? g_ctx : A;

    const int tid  = threadIdx.x;
    const int lane = tid & 31;
    const int warp = tid >> 5;
    const int wm   = warp & 1;    // 0..1
    const int wn   = warp >> 1;   // 0..3
    const int m0   = blockIdx.x * 128;
    const int n0   = blockIdx.y * 128;

    float c[4][4][4];
#pragma unroll
    for (int i = 0; i < 4; i++)
#pragma unroll
        for (int j = 0; j < 4; j++)
#pragma unroll
            for (int k = 0; k < 4; k++) c[i][j][k] = 0.f;

    for (int k0 = 0; k0 < 1024; k0 += 16) {
        // cooperative load + tf32 hi/lo split
#pragma unroll
        for (int i = 0; i < 2; i++) {
            int lin = tid + i * 256;          // 0..511 float4 slots
            int r   = lin >> 2;               // 0..127
            int c4  = (lin & 3) * 4;          // 0,4,8,12
            float4 av = *(const float4*)(Ap + (size_t)(m0 + r) * 1024 + k0 + c4);
            float4 ah, al;
            ah.x = tf32_hi(av.x); al.x = av.x - ah.x;
            ah.y = tf32_hi(av.y); al.y = av.y - ah.y;
            ah.z = tf32_hi(av.z); al.z = av.z - ah.z;
            ah.w = tf32_hi(av.w); al.w = av.w - ah.w;
            *(float4*)(As_h + r * 20 + c4) = ah;
            *(float4*)(As_l + r * 20 + c4) = al;

            float4 bvv = *(const float4*)(W + (size_t)(n0 + r) * 1024 + k0 + c4);
            float4 bh, bl;
            bh.x = tf32_hi(bvv.x); bl.x = bvv.x - bh.x;
            bh.y = tf32_hi(bvv.y); bl.y = bvv.y - bh.y;
            bh.z = tf32_hi(bvv.z); bl.z = bvv.z - bh.z;
            bh.w = tf32_hi(bvv.w); bl.w = bvv.w - bh.w;
            *(float4*)(Bs_h + r * 20 + c4) = bh;
            *(float4*)(Bs_l + r * 20 + c4) = bl;
        }
        __syncthreads();

#pragma unroll
        for (int kg = 0; kg < 16; kg += 8) {
            uint32_t bh[4][2], bl[4][2];
#pragma unroll
            for (int nt = 0; nt < 4; nt++) {
                int boff = (wn * 32 + nt * 8 + (lane >> 2)) * 20 + kg + (lane & 3);
                bh[nt][0] = __float_as_uint(Bs_h[boff]);
                bh[nt][1] = __float_as_uint(Bs_h[boff + 4]);
                bl[nt][0] = __float_as_uint(Bs_l[boff]);
                bl[nt][1] = __float_as_uint(Bs_l[boff + 4]);
            }
#pragma unroll
            for (int mt = 0; mt < 4; mt++) {
                int aoff = (wm * 64 + mt * 16 + (lane >> 2)) * 20 + kg + (lane & 3);
                uint32_t ah0 = __float_as_uint(As_h[aoff]);
                uint32_t ah1 = __float_as_uint(As_h[aoff + 8 * 20]);
                uint32_t ah2 = __float_as_uint(As_h[aoff + 4]);
                uint32_t ah3 = __float_as_uint(As_h[aoff + 8 * 20 + 4]);
                uint32_t al0 = __float_as_uint(As_l[aoff]);
                uint32_t al1 = __float_as_uint(As_l[aoff + 8 * 20]);
                uint32_t al2 = __float_as_uint(As_l[aoff + 4]);
                uint32_t al3 = __float_as_uint(As_l[aoff + 8 * 20 + 4]);
#pragma unroll
                for (int nt = 0; nt < 4; nt++) {
                    mma_tf32(c[mt][nt], ah0, ah1, ah2, ah3, bh[nt][0], bh[nt][1]);
                    mma_tf32(c[mt][nt], ah0, ah1, ah2, ah3, bl[nt][0], bl[nt][1]);
                    mma_tf32(c[mt][nt], al0, al1, al2, al3, bh[nt][0], bh[nt][1]);
                }
            }
        }
        __syncthreads();
    }

    // epilogue
#pragma unroll
    for (int mt = 0; mt < 4; mt++) {
#pragma unroll
        for (int nt = 0; nt < 4; nt++) {
#pragma unroll
            for (int j = 0; j < 4; j++) {
                int row = m0 + wm * 64 + mt * 16 + (lane >> 2) + ((j >> 1) << 3);
                int col = n0 + wn * 32 + nt * 8 + 2 * (lane & 3) + (j & 1);
                float v = c[mt][nt][j] + bias[col];
                if (mode == 3) {
                    g_dense[(size_t)row * 1024 + col] = v > 0.f ? v : 0.f;
                } else {
                    int b  = row >> 11;
                    int s  = row & 2047;
                    int h  = col >> 6;
                    int dk = col & 63;
                    float* dst = (mode == 0) ? g_qx : (mode == 1) ? g_kx : g_vx;
                    dst[(((size_t)(b * H_ + h)) * S_ + s) * DK_ + dk] = v;
                }
            }
        }
    }
}

// ---------------------------------------------------------------------------
// Fused attention kernel.
// grid = (S/64, H*B), block = 256 threads (8 warps as 4(m) x 2(n), warp 16x32)
// Per block: Q tile (64 rows) resident; loop over 32 k-tiles of 64:
//   S = Q K^T (tf32 1x) -> P = exp(S) -> write unnorm P to attn gmem,
//   accumulate rowsum (smem atomics) and O += P @ V (3xTF32).
// Epilogue: O * (1/rowsum) -> g_ctx; store 1/rowsum to g_rinv.
// ---------------------------------------------------------------------------
#define ATTN_SMEM_FLOATS (6 * 64 * 68 + 64)

__global__ __launch_bounds__(256) void attn_kernel(float* __restrict__ attn_out) {
    extern __shared__ float smf[];
    float* Qh  = smf;                 // 64x68 (tf32 hi, pre-scaled by 1/TEMP)
    float* Kh  = Qh + 64 * 68;        // 64x68 (tf32 hi)
    float* Vth = Kh + 64 * 68;        // transposed V hi: [d][kk]
    float* Vtl = Vth + 64 * 68;       // transposed V lo
    float* Ph  = Vtl + 64 * 68;       // P hi
    float* Pl  = Ph + 64 * 68;        // P lo
    float* rs  = Pl + 64 * 68;        // rowsum[64]

    const int tid  = threadIdx.x;
    const int lane = tid & 31;
    const int warp = tid >> 5;
    const int wm   = warp & 3;        // 0..3 -> q rows wm*16
    const int wn   = warp >> 2;       // 0..1 -> cols wn*32
    const int hb   = blockIdx.y;
    const int h    = hb >> 1;         // hb = h*B + b, B=2
    const int b    = hb & 1;
    const int q0   = blockIdx.x * 64;

    const float* qbase = g_qx + ((size_t)(b * H_ + h)) * S_ * DK_;
    const float* kbase = g_kx + ((size_t)(b * H_ + h)) * S_ * DK_;
    const float* vbase = g_vx + ((size_t)(b * H_ + h)) * S_ * DK_;
    const float invT = 0.03125f;      // 1/sqrt(1024)

    // load Q tile once (hi only, pre-scaled)
#pragma unroll
    for (int i = 0; i < 4; i++) {
        int lin = tid + i * 256;      // float4 index 0..1023
        int r   = lin >> 4;
        int c4  = (lin & 15) * 4;
        float4 v = *(const float4*)(qbase + (size_t)(q0 + r) * 64 + c4);
        float4 o;
        o.x = tf32_hi(v.x * invT);
        o.y = tf32_hi(v.y * invT);
        o.z = tf32_hi(v.z * invT);
        o.w = tf32_hi(v.w * invT);
        *(float4*)(Qh + r * 68 + c4) = o;
    }
    if (tid < 64) rs[tid] = 0.f;

    float o[4][4];
#pragma unroll
    for (int i = 0; i < 4; i++)
#pragma unroll
        for (int j = 0; j < 4; j++) o[i][j] = 0.f;

    for (int kt = 0; kt < 32; kt++) {
        const int k0 = kt * 64;
        // load K (hi) and V (transposed, hi/lo)
#pragma unroll
        for (int i = 0; i < 4; i++) {
            int lin = tid + i * 256;
            int r   = lin >> 4;
            int c4  = (lin & 15) * 4;
            float4 kv = *(const float4*)(kbase + (size_t)(k0 + r) * 64 + c4);
            float4 ko;
            ko.x = tf32_hi(kv.x); ko.y = tf32_hi(kv.y);
            ko.z = tf32_hi(kv.z); ko.w = tf32_hi(kv.w);
            *(float4*)(Kh + r * 68 + c4) = ko;

            float4 vv = *(const float4*)(vbase + (size_t)(k0 + r) * 64 + c4);
            float hx;
            hx = tf32_hi(vv.x); Vth[(c4 + 0) * 68 + r] = hx; Vtl[(c4 + 0) * 68 + r] = vv.x - hx;
            hx = tf32_hi(vv.y); Vth[(c4 + 1) * 68 + r] = hx; Vtl[(c4 + 1) * 68 + r] = vv.y - hx;
            hx = tf32_hi(vv.z); Vth[(c4 + 2) * 68 + r] = hx; Vtl[(c4 + 2) * 68 + r] = vv.z - hx;
            hx = tf32_hi(vv.w); Vth[(c4 + 3) * 68 + r] = hx; Vtl[(c4 + 3) * 68 + r] = vv.w - hx;
        }
        __syncthreads();

        // scores: S = Qs * K^T  (1x tf32)
        float s[4][4];
#pragma unroll
        for (int i = 0; i < 4; i++)
#pragma unroll
            for (int j = 0; j < 4; j++) s[i][j] = 0.f;

#pragma unroll
        for (int kg = 0; kg < 64; kg += 8) {
            int aoff = (wm * 16 + (lane >> 2)) * 68 + kg + (lane & 3);
            uint32_t a0 = __float_as_uint(Qh[aoff]);
            uint32_t a1 = __float_as_uint(Qh[aoff + 8 * 68]);
            uint32_t a2 = __float_as_uint(Qh[aoff + 4]);
            uint32_t a3 = __float_as_uint(Qh[aoff + 8 * 68 + 4]);
#pragma unroll
            for (int nt = 0; nt < 4; nt++) {
                int boff = (wn * 32 + nt * 8 + (lane >> 2)) * 68 + kg + (lane & 3);
                mma_tf32(s[nt], a0, a1, a2, a3,
                         __float_as_uint(Kh[boff]), __float_as_uint(Kh[boff + 4]));
            }
        }

        // exp, P hi/lo to smem, rowsum partials
        float rlo = 0.f, rhi = 0.f;
        const int rowb = wm * 16 + (lane >> 2);
#pragma unroll
        for (int nt = 0; nt < 4; nt++) {
            int colb = wn * 32 + nt * 8 + 2 * (lane & 3);
#pragma unroll
            for (int j = 0; j < 4; j++) {
                float p = __expf(s[nt][j]);
                int row = rowb + ((j >> 1) << 3);
                int col = colb + (j & 1);
                float ph = tf32_hi(p);
                Ph[row * 68 + col] = ph;
                Pl[row * 68 + col] = p - ph;
                if (j < 2) rlo += p; else rhi += p;
            }
        }
        rlo += __shfl_xor_sync(0xffffffffu, rlo, 1);
        rlo += __shfl_xor_sync(0xffffffffu, rlo, 2);
        rhi += __shfl_xor_sync(0xffffffffu, rhi, 1);
        rhi += __shfl_xor_sync(0xffffffffu, rhi, 2);
        if ((lane & 3) == 0) {
            atomicAdd(&rs[rowb], rlo);
            atomicAdd(&rs[rowb + 8], rhi);
        }
        __syncthreads();

        // write unnormalized P to gmem (coalesced float4)
        float* ab = attn_out + ((size_t)hb * S_ + q0) * S_ + k0;
#pragma unroll
        for (int i = 0; i < 4; i++) {
            int lin = tid + i * 256;
            int r   = lin >> 4;
            int c4  = (lin & 15) * 4;
            float4 pv;
            pv.x = Ph[r * 68 + c4 + 0] + Pl[r * 68 + c4 + 0];
            pv.y = Ph[r * 68 + c4 + 1] + Pl[r * 68 + c4 + 1];
            pv.z = Ph[r * 68 + c4 + 2] + Pl[r * 68 + c4 + 2];
            pv.w = Ph[r * 68 + c4 + 3] + Pl[r * 68 + c4 + 3];
            *(float4*)(ab + (size_t)r * S_ + c4) = pv;
        }

        // O += P @ V  (3xTF32)
#pragma unroll
        for (int kg = 0; kg < 64; kg += 8) {
            int aoff = (wm * 16 + (lane >> 2)) * 68 + kg + (lane & 3);
            uint32_t ah0 = __float_as_uint(Ph[aoff]);
            uint32_t ah1 = __float_as_uint(Ph[aoff + 8 * 68]);
            uint32_t ah2 = __float_as_uint(Ph[aoff + 4]);
            uint32_t ah3 = __float_as_uint(Ph[aoff + 8 * 68 + 4]);
            uint32_t al0 = __float_as_uint(Pl[aoff]);
            uint32_t al1 = __float_as_uint(Pl[aoff + 8 * 68]);
            uint32_t al2 = __float_as_uint(Pl[aoff + 4]);
            uint32_t al3 = __float_as_uint(Pl[aoff + 8 * 68 + 4]);
#pragma unroll
            for (int nt = 0; nt < 4; nt++) {
                int boff = (wn * 32 + nt * 8 + (lane >> 2)) * 68 + kg + (lane & 3);
                uint32_t bh0 = __float_as_uint(Vth[boff]);
                uint32_t bh1 = __float_as_uint(Vth[boff + 4]);
                uint32_t bl0 = __float_as_uint(Vtl[boff]);
                uint32_t bl1 = __float_as_uint(Vtl[boff + 4]);
                mma_tf32(o[nt], ah0, ah1, ah2, ah3, bh0, bh1);
                mma_tf32(o[nt], ah0, ah1, ah2, ah3, bl0, bl1);
                mma_tf32(o[nt], al0, al1, al2, al3, bh0, bh1);
            }
        }
        __syncthreads();
    }

    // invert rowsums once; publish for the normalize pass
    if (tid < 64) {
        float inv = 1.0f / rs[tid];
        g_rinv[(size_t)hb * S_ + q0 + tid] = inv;
        rs[tid] = inv;
    }
    __syncthreads();

    // write ctx = O * inv(rowsum), layout [b*S+s][h*64+d]
    const int rowb = wm * 16 + (lane >> 2);
#pragma unroll
    for (int nt = 0; nt < 4; nt++) {
        int colb = wn * 32 + nt * 8 + 2 * (lane & 3);
#pragma unroll
        for (int j = 0; j < 4; j++) {
            int row = rowb + ((j >> 1) << 3);
            int col = colb + (j & 1);
            float v = o[nt][j] * rs[row];
            g_ctx[((size_t)(b * S_ + q0 + row)) * D_ + h * DK_ + col] = v;
        }
    }
}

// ---------------------------------------------------------------------------
// Normalize attn in place: attn[hb][q][k] *= g_rinv[hb*S+q]
// ---------------------------------------------------------------------------
__global__ __launch_bounds__(256) void attn_norm(float* __restrict__ attn) {
    size_t i = (size_t)blockIdx.x * 256 + threadIdx.x;  // float4 index
    float inv = g_rinv[i >> 9];                          // 512 float4 per row
    float4* p = (float4*)attn;
    float4 v = p[i];
    v.x *= inv; v.y *= inv; v.z *= inv; v.w *= inv;
    p[i] = v;
}

// ---------------------------------------------------------------------------
// LayerNorm over rows of g_dense -> out
// ---------------------------------------------------------------------------
__global__ __launch_bounds__(256) void ln_kernel(const float* __restrict__ lg,
                                                 const float* __restrict__ lb,
                                                 float* __restrict__ out) {
    const int row = blockIdx.x;
    const int tid = threadIdx.x;
    const float* x = g_dense + (size_t)row * 1024;
    float4 xv = *(const float4*)(x + tid * 4);
    float s  = xv.x + xv.y + xv.z + xv.w;
    float ss = fmaf(xv.x, xv.x, fmaf(xv.y, xv.y, fmaf(xv.z, xv.z, xv.w * xv.w)));
#pragma unroll
    for (int off = 16; off > 0; off >>= 1) {
        s  += __shfl_xor_sync(0xffffffffu, s, off);
        ss += __shfl_xor_sync(0xffffffffu, ss, off);
    }
    __shared__ float sm1[8], sm2[8];
    if ((tid & 31) == 0) { sm1[tid >> 5] = s; sm2[tid >> 5] = ss; }
    __syncthreads();
    if (tid < 32) {
        float a  = (tid < 8) ? sm1[tid] : 0.f;
        float b2 = (tid < 8) ? sm2[tid] : 0.f;
#pragma unroll
        for (int off = 4; off > 0; off >>= 1) {
            a  += __shfl_xor_sync(0xffffffffu, a, off);
            b2 += __shfl_xor_sync(0xffffffffu, b2, off);
        }
        if (tid == 0) { sm1[0] = a; sm2[0] = b2; }
    }
    __syncthreads();
    float mean = sm1[0] * (1.0f / 1024.0f);
    float var  = sm2[0] * (1.0f / 1024.0f) - mean * mean;
    float rstd = rsqrtf(var + 1e-5f);
    float4 gv = *(const float4*)(lg + tid * 4);
    float4 bv = *(const float4*)(lb + tid * 4);
    float4 ov;
    ov.x = (xv.x - mean) * rstd * gv.x + bv.x;
    ov.y = (xv.y - mean) * rstd * gv.y + bv.y;
    ov.z = (xv.z - mean) * rstd * gv.z + bv.z;
    ov.w = (xv.w - mean) * rstd * gv.w + bv.w;
    *(float4*)(out + (size_t)row * 1024 + tid * 4) = ov;
}

// ---------------------------------------------------------------------------
// Launch
// ---------------------------------------------------------------------------
extern "C" void kernel_launch(void* const* d_in, const int* in_sizes, int n_in,
                              void* d_out, int out_size) {
    const float* k_in = (const float*)d_in[0];
    const float* q_in = (const float*)d_in[1];
    const float* wk   = (const float*)d_in[2];
    const float* bk   = (const float*)d_in[3];
    const float* wq   = (const float*)d_in[4];
    const float* bq   = (const float*)d_in[5];
    const float* wv   = (const float*)d_in[6];
    const float* bv   = (const float*)d_in[7];
    const float* wd   = (const float*)d_in[8];
    const float* bd   = (const float*)d_in[9];
    const float* lg   = (const float*)d_in[10];
    const float* lb   = (const float*)d_in[11];

    float* out  = (float*)d_out;
    float* attn = out + (size_t)B_ * S_ * D_;  // tuple order: (out, attn)

    const int attn_smem_bytes = ATTN_SMEM_FLOATS * 4;  // ~104.7 KB
    cudaFuncSetAttribute(attn_kernel, cudaFuncAttributeMaxDynamicSharedMemorySize,
                         attn_smem_bytes);

    dim3 pgrid(MTOT / 128, D_ / 128);  // (32, 8)
    proj_gemm<<<pgrid, 256>>>(q_in, wq, bq, 0);   // g_qx
    proj_gemm<<<pgrid, 256>>>(k_in, wk, bk, 1);   // g_kx
    proj_gemm<<<pgrid, 256>>>(k_in, wv, bv, 2);   // g_vx (v = k)

    attn_kernel<<<dim3(S_ / 64, HB_), 256, attn_smem_bytes>>>(attn);

    // 32*2048*2048/4 float4 = 33,554,432 -> 131072 blocks of 256
    attn_norm<<<131072, 256>>>(attn);

    proj_gemm<<<pgrid, 256>>>(nullptr, wd, bd, 3);  // dense + relu -> g_dense
    ln_kernel<<<MTOT, 256>>>(lg, lb, out);
}

// round 6
// speedup vs baseline: 1.2518x; 1.2518x over previous
#include <cuda_runtime.h>
#include <cstdint>
#include <cstddef>

// Problem constants
#define B_    2
#define S_    2048
#define D_    1024
#define H_    16
#define DK_   64
#define MTOT  4096        // B_*S_
#define HB_   32          // H_*B_

// ---------------------------------------------------------------------------
// Scratch (static device allocations; no dynamic alloc allowed)
// ---------------------------------------------------------------------------
static __device__ float g_qx[B_ * H_ * S_ * DK_];   // [b][h][s][dk]
static __device__ float g_kx[B_ * H_ * S_ * DK_];
static __device__ float g_vx[B_ * H_ * S_ * DK_];
static __device__ float g_ctx[(size_t)MTOT * D_];   // [b*S+s][h*64+dk]
static __device__ float g_dense[(size_t)MTOT * D_];
static __device__ float g_rinv[HB_ * S_];           // 1/rowsum per attn row
static __device__ float g_vcs[HB_ * DK_];           // colsum of V per (b*H+h, d)

// ---------------------------------------------------------------------------
// Helpers
// ---------------------------------------------------------------------------
__device__ __forceinline__ float tf32_hi(float x) {
    uint32_t r;
    asm("cvt.rna.tf32.f32 %0, %1;" : "=r"(r) : "f"(x));
    return __uint_as_float(r);
}

__device__ __forceinline__ void mma_tf32(float c[4],
                                         uint32_t a0, uint32_t a1, uint32_t a2, uint32_t a3,
                                         uint32_t b0, uint32_t b1) {
    asm volatile(
        "mma.sync.aligned.m16n8k8.row.col.f32.tf32.tf32.f32 "
        "{%0,%1,%2,%3}, {%4,%5,%6,%7}, {%8,%9}, {%0,%1,%2,%3};\n"
        : "+f"(c[0]), "+f"(c[1]), "+f"(c[2]), "+f"(c[3])
        : "r"(a0), "r"(a1), "r"(a2), "r"(a3), "r"(b0), "r"(b1));
}

// ---------------------------------------------------------------------------
// Generic 3xTF32 GEMM:  C[4096 x 1024] = A[4096 x 1024] @ W[1024 x 1024]^T + bias
// mode 0/1/2 : scatter into g_qx/g_kx/g_vx as [b][h][s][dk]
// mode 3     : A = g_ctx (arg ignored), out = relu(C) into g_dense row-major
// ---------------------------------------------------------------------------
__global__ __launch_bounds__(256) void proj_gemm(const float* __restrict__ A,
                                                 const float* __restrict__ W,
                                                 const float* __restrict__ bias,
                                                 int mode) {
    __shared__ float As_h[128 * 20];
    __shared__ float As_l[128 * 20];
    __shared__ float Bs_h[128 * 20];
    __shared__ float Bs_l[128 * 20];

    const float* Ap = (mode == 3) ? g_ctx : A;

    const int tid  = threadIdx.x;
    const int lane = tid & 31;
    const int warp = tid >> 5;
    const int wm   = warp & 1;
    const int wn   = warp >> 1;
    const int m0   = blockIdx.x * 128;
    const int n0   = blockIdx.y * 128;

    float c[4][4][4];
#pragma unroll
    for (int i = 0; i < 4; i++)
#pragma unroll
        for (int j = 0; j < 4; j++)
#pragma unroll
            for (int k = 0; k < 4; k++) c[i][j][k] = 0.f;

    for (int k0 = 0; k0 < 1024; k0 += 16) {
#pragma unroll
        for (int i = 0; i < 2; i++) {
            int lin = tid + i * 256;
            int r   = lin >> 2;
            int c4  = (lin & 3) * 4;
            float4 av = *(const float4*)(Ap + (size_t)(m0 + r) * 1024 + k0 + c4);
            float4 ah, al;
            ah.x = tf32_hi(av.x); al.x = av.x - ah.x;
            ah.y = tf32_hi(av.y); al.y = av.y - ah.y;
            ah.z = tf32_hi(av.z); al.z = av.z - ah.z;
            ah.w = tf32_hi(av.w); al.w = av.w - ah.w;
            *(float4*)(As_h + r * 20 + c4) = ah;
            *(float4*)(As_l + r * 20 + c4) = al;

            float4 bvv = *(const float4*)(W + (size_t)(n0 + r) * 1024 + k0 + c4);
            float4 bh, bl;
            bh.x = tf32_hi(bvv.x); bl.x = bvv.x - bh.x;
            bh.y = tf32_hi(bvv.y); bl.y = bvv.y - bh.y;
            bh.z = tf32_hi(bvv.z); bl.z = bvv.z - bh.z;
            bh.w = tf32_hi(bvv.w); bl.w = bvv.w - bh.w;
            *(float4*)(Bs_h + r * 20 + c4) = bh;
            *(float4*)(Bs_l + r * 20 + c4) = bl;
        }
        __syncthreads();

#pragma unroll
        for (int kg = 0; kg < 16; kg += 8) {
            uint32_t bh[4][2], bl[4][2];
#pragma unroll
            for (int nt = 0; nt < 4; nt++) {
                int boff = (wn * 32 + nt * 8 + (lane >> 2)) * 20 + kg + (lane & 3);
                bh[nt][0] = __float_as_uint(Bs_h[boff]);
                bh[nt][1] = __float_as_uint(Bs_h[boff + 4]);
                bl[nt][0] = __float_as_uint(Bs_l[boff]);
                bl[nt][1] = __float_as_uint(Bs_l[boff + 4]);
            }
#pragma unroll
            for (int mt = 0; mt < 4; mt++) {
                int aoff = (wm * 64 + mt * 16 + (lane >> 2)) * 20 + kg + (lane & 3);
                uint32_t ah0 = __float_as_uint(As_h[aoff]);
                uint32_t ah1 = __float_as_uint(As_h[aoff + 8 * 20]);
                uint32_t ah2 = __float_as_uint(As_h[aoff + 4]);
                uint32_t ah3 = __float_as_uint(As_h[aoff + 8 * 20 + 4]);
                uint32_t al0 = __float_as_uint(As_l[aoff]);
                uint32_t al1 = __float_as_uint(As_l[aoff + 8 * 20]);
                uint32_t al2 = __float_as_uint(As_l[aoff + 4]);
                uint32_t al3 = __float_as_uint(As_l[aoff + 8 * 20 + 4]);
#pragma unroll
                for (int nt = 0; nt < 4; nt++) {
                    mma_tf32(c[mt][nt], ah0, ah1, ah2, ah3, bh[nt][0], bh[nt][1]);
                    mma_tf32(c[mt][nt], ah0, ah1, ah2, ah3, bl[nt][0], bl[nt][1]);
                    mma_tf32(c[mt][nt], al0, al1, al2, al3, bh[nt][0], bh[nt][1]);
                }
            }
        }
        __syncthreads();
    }

#pragma unroll
    for (int mt = 0; mt < 4; mt++) {
#pragma unroll
        for (int nt = 0; nt < 4; nt++) {
#pragma unroll
            for (int j = 0; j < 4; j++) {
                int row = m0 + wm * 64 + mt * 16 + (lane >> 2) + ((j >> 1) << 3);
                int col = n0 + wn * 32 + nt * 8 + 2 * (lane & 3) + (j & 1);
                float v = c[mt][nt][j] + bias[col];
                if (mode == 3) {
                    g_dense[(size_t)row * 1024 + col] = v > 0.f ? v : 0.f;
                } else {
                    int b  = row >> 11;
                    int s  = row & 2047;
                    int h  = col >> 6;
                    int dk = col & 63;
                    float* dst = (mode == 0) ? g_qx : (mode == 1) ? g_kx : g_vx;
                    dst[(((size_t)(b * H_ + h)) * S_ + s) * DK_ + dk] = v;
                }
            }
        }
    }
}

// ---------------------------------------------------------------------------
// V column-sum per (b*H+h, d):  g_vcs[bh][d] = sum_s g_vx[bh][s][d]
// ---------------------------------------------------------------------------
__global__ __launch_bounds__(256) void vcs_kernel() {
    const int bh = blockIdx.x;
    const float* vb = g_vx + (size_t)bh * S_ * DK_;
    const int d = threadIdx.x & 63;
    const int c = threadIdx.x >> 6;   // 0..3
    float s = 0.f;
    for (int r = c * 512; r < (c + 1) * 512; r++) s += vb[(size_t)r * 64 + d];
    __shared__ float sm[256];
    sm[threadIdx.x] = s;
    __syncthreads();
    if (threadIdx.x < 64)
        g_vcs[bh * 64 + threadIdx.x] =
            sm[threadIdx.x] + sm[threadIdx.x + 64] + sm[threadIdx.x + 128] + sm[threadIdx.x + 192];
}

// ---------------------------------------------------------------------------
// Fused attention kernel (v2, smem-traffic-minimized).
// grid = (S/64, H*B), block = 256 (8 warps: wm in 0..3 = q-rows, wn in 0..1 = k-half)
// Q fragments live in registers for the whole kernel. Per 64-wide kv tile:
//   stage K (tf32) stride 68, V (raw) stride 72 in smem
//   S = Q K^T (tf32) -> p = exp(S): written straight to gmem attn (unnormalized),
//   rowsums accumulated in registers, dp = p-1 staged in a per-warp smem buffer
//   O_half += dp @ V (1x tf32, warp contracts only its own 32-k half)
// Epilogue: O = O_half(wn=0)+O_half(wn=1) + colsumV, scaled by 1/rowsum -> g_ctx.
// ---------------------------------------------------------------------------
#define KSTR 68
#define VSTR 72
#define PSTR 36
#define OSTR 66
#define ATTN_SMEM_FLOATS (64 * KSTR + 64 * VSTR + 8 * 16 * PSTR + 64)

__global__ __launch_bounds__(256, 2) void attn_kernel(float* __restrict__ attn_out) {
    extern __shared__ float smf[];
    float* Kh   = smf;                       // 64 x 68 (tf32-rounded K)
    float* Vs   = Kh + 64 * KSTR;            // 64 x 72 (raw V)
    float* Pb   = Vs + 64 * VSTR;            // 8 warps x 16 x 36 (dp buffer)
    float* rs   = Pb + 8 * 16 * PSTR;        // rowsum[64]
    float* Obuf = smf;                       // epilogue alias: 2 x 64 x 66 (8448 <= 8960)

    const int tid  = threadIdx.x;
    const int lane = tid & 31;
    const int warp = tid >> 5;
    const int wm   = warp & 3;               // q-row group
    const int wn   = warp >> 2;              // k half
    const int g    = lane >> 2;
    const int j    = lane & 3;
    const int hb   = blockIdx.y;             // h*B + b
    const int h    = hb >> 1;
    const int b    = hb & 1;
    const int q0   = blockIdx.x * 64;

    const float* qbase = g_qx + ((size_t)(b * H_ + h)) * S_ * DK_;
    const float* kbase = g_kx + ((size_t)(b * H_ + h)) * S_ * DK_;
    const float* vbase = g_vx + ((size_t)(b * H_ + h)) * S_ * DK_;
    const float invT = 0.03125f;             // 1/sqrt(1024)

    if (tid < 64) rs[tid] = 0.f;

    // Q fragments in registers: rows (wm*16+g, +8), cols kg*8+j, +4; pre-scaled
    uint32_t qa[8][4];
    {
        const float* qr0 = qbase + (size_t)(q0 + wm * 16 + g) * 64;
        const float* qr1 = qr0 + 8 * 64;
#pragma unroll
        for (int kg = 0; kg < 8; kg++) {
            qa[kg][0] = __float_as_uint(tf32_hi(qr0[kg * 8 + j] * invT));
            qa[kg][1] = __float_as_uint(tf32_hi(qr1[kg * 8 + j] * invT));
            qa[kg][2] = __float_as_uint(tf32_hi(qr0[kg * 8 + j + 4] * invT));
            qa[kg][3] = __float_as_uint(tf32_hi(qr1[kg * 8 + j + 4] * invT));
        }
    }

    float o[8][4];
#pragma unroll
    for (int i = 0; i < 8; i++)
#pragma unroll
        for (int k = 0; k < 4; k++) o[i][k] = 0.f;
    float rs0 = 0.f, rs1 = 0.f;
    float* Pw = Pb + warp * 16 * PSTR;

    for (int kt = 0; kt < 32; kt++) {
        const int k0 = kt * 64;
        // stage K (tf32) and V (raw)
#pragma unroll
        for (int i = 0; i < 4; i++) {
            int lin = tid + i * 256;
            int r   = lin >> 4;
            int c4  = (lin & 15) * 4;
            float4 kv = *(const float4*)(kbase + (size_t)(k0 + r) * 64 + c4);
            float4 ko;
            ko.x = tf32_hi(kv.x); ko.y = tf32_hi(kv.y);
            ko.z = tf32_hi(kv.z); ko.w = tf32_hi(kv.w);
            *(float4*)(Kh + r * KSTR + c4) = ko;
            *(float4*)(Vs + r * VSTR + c4) =
                *(const float4*)(vbase + (size_t)(k0 + r) * 64 + c4);
        }
        __syncthreads();

        // scores: 16 q-rows x 32 kv (this warp's half)
        float s[4][4];
#pragma unroll
        for (int i = 0; i < 4; i++)
#pragma unroll
            for (int k = 0; k < 4; k++) s[i][k] = 0.f;
#pragma unroll
        for (int kg = 0; kg < 8; kg++) {
#pragma unroll
            for (int nt = 0; nt < 4; nt++) {
                int boff = (wn * 32 + nt * 8 + g) * KSTR + kg * 8 + j;
                mma_tf32(s[nt], qa[kg][0], qa[kg][1], qa[kg][2], qa[kg][3],
                         __float_as_uint(Kh[boff]), __float_as_uint(Kh[boff + 4]));
            }
        }

        // exp -> gmem attn (unnormalized), rowsum regs, dp -> warp smem buffer
        float* ab = attn_out + ((size_t)hb * S_ + q0 + wm * 16 + g) * S_ + k0 + wn * 32;
#pragma unroll
        for (int nt = 0; nt < 4; nt++) {
            float p0 = __expf(s[nt][0]);
            float p1 = __expf(s[nt][1]);
            float p2 = __expf(s[nt][2]);
            float p3 = __expf(s[nt][3]);
            rs0 += p0 + p1;
            rs1 += p2 + p3;
            *(float2*)(ab + nt * 8 + 2 * j) = make_float2(p0, p1);
            *(float2*)(ab + (size_t)8 * S_ + nt * 8 + 2 * j) = make_float2(p2, p3);
            *(float2*)(Pw + g * PSTR + nt * 8 + 2 * j)       = make_float2(p0 - 1.f, p1 - 1.f);
            *(float2*)(Pw + (g + 8) * PSTR + nt * 8 + 2 * j) = make_float2(p2 - 1.f, p3 - 1.f);
        }
        __syncwarp();

        // O_half += dp @ V over this warp's 32-k half
#pragma unroll
        for (int kp = 0; kp < 4; kp++) {
            uint32_t a0 = __float_as_uint(Pw[g * PSTR + kp * 8 + j]);
            uint32_t a1 = __float_as_uint(Pw[(g + 8) * PSTR + kp * 8 + j]);
            uint32_t a2 = __float_as_uint(Pw[g * PSTR + kp * 8 + j + 4]);
            uint32_t a3 = __float_as_uint(Pw[(g + 8) * PSTR + kp * 8 + j + 4]);
#pragma unroll
            for (int nv = 0; nv < 8; nv++) {
                int boff = (wn * 32 + kp * 8 + j) * VSTR + nv * 8 + g;
                mma_tf32(o[nv], a0, a1, a2, a3,
                         __float_as_uint(Vs[boff]), __float_as_uint(Vs[boff + 4 * VSTR]));
            }
        }
        __syncthreads();
    }

    // --- epilogue ---
    // dump O halves into Obuf (aliases K/V region; all K/V reads are done)
    float* Ob = Obuf + wn * 64 * OSTR + (wm * 16) * OSTR;
#pragma unroll
    for (int nv = 0; nv < 8; nv++) {
        *(float2*)(Ob + g * OSTR + nv * 8 + 2 * j)       = make_float2(o[nv][0], o[nv][1]);
        *(float2*)(Ob + (g + 8) * OSTR + nv * 8 + 2 * j) = make_float2(o[nv][2], o[nv][3]);
    }
    // rowsum reduction: quad lanes then across wn warps
    rs0 += __shfl_xor_sync(0xffffffffu, rs0, 1);
    rs0 += __shfl_xor_sync(0xffffffffu, rs0, 2);
    rs1 += __shfl_xor_sync(0xffffffffu, rs1, 1);
    rs1 += __shfl_xor_sync(0xffffffffu, rs1, 2);
    if (j == 0) {
        atomicAdd(&rs[wm * 16 + g], rs0);
        atomicAdd(&rs[wm * 16 + 8 + g], rs1);
    }
    __syncthreads();
    if (tid < 64) {
        float inv = 1.0f / rs[tid];
        g_rinv[(size_t)hb * S_ + q0 + tid] = inv;
        rs[tid] = inv;
    }
    __syncthreads();

    const float* vc = g_vcs + (b * H_ + h) * 64;
#pragma unroll
    for (int i = 0; i < 16; i++) {
        int lin = tid + i * 256;
        int qr  = lin >> 6;
        int d   = lin & 63;
        float val = (Obuf[qr * OSTR + d] + Obuf[64 * OSTR + qr * OSTR + d] + vc[d]) * rs[qr];
        g_ctx[((size_t)(b * S_ + q0 + qr)) * D_ + h * 64 + d] = val;
    }
}

// ---------------------------------------------------------------------------
// Normalize attn in place: attn[hb][q][k] *= g_rinv[hb*S+q]
// ---------------------------------------------------------------------------
__global__ __launch_bounds__(256) void attn_norm(float* __restrict__ attn) {
    size_t i = (size_t)blockIdx.x * 256 + threadIdx.x;  // float4 index
    float inv = g_rinv[i >> 9];                          // 512 float4 per row
    float4* p = (float4*)attn;
    float4 v = p[i];
    v.x *= inv; v.y *= inv; v.z *= inv; v.w *= inv;
    p[i] = v;
}

// ---------------------------------------------------------------------------
// LayerNorm over rows of g_dense -> out
// ---------------------------------------------------------------------------
__global__ __launch_bounds__(256) void ln_kernel(const float* __restrict__ lg,
                                                 const float* __restrict__ lb,
                                                 float* __restrict__ out) {
    const int row = blockIdx.x;
    const int tid = threadIdx.x;
    const float* x = g_dense + (size_t)row * 1024;
    float4 xv = *(const float4*)(x + tid * 4);
    float s  = xv.x + xv.y + xv.z + xv.w;
    float ss = fmaf(xv.x, xv.x, fmaf(xv.y, xv.y, fmaf(xv.z, xv.z, xv.w * xv.w)));
#pragma unroll
    for (int off = 16; off > 0; off >>= 1) {
        s  += __shfl_xor_sync(0xffffffffu, s, off);
        ss += __shfl_xor_sync(0xffffffffu, ss, off);
    }
    __shared__ float sm1[8], sm2[8];
    if ((tid & 31) == 0) { sm1[tid >> 5] = s; sm2[tid >> 5] = ss; }
    __syncthreads();
    if (tid < 32) {
        float a  = (tid < 8) ? sm1[tid] : 0.f;
        float b2 = (tid < 8) ? sm2[tid] : 0.f;
#pragma unroll
        for (int off = 4; off > 0; off >>= 1) {
            a  += __shfl_xor_sync(0xffffffffu, a, off);
            b2 += __shfl_xor_sync(0xffffffffu, b2, off);
        }
        if (tid == 0) { sm1[0] = a; sm2[0] = b2; }
    }
    __syncthreads();
    float mean = sm1[0] * (1.0f / 1024.0f);
    float var  = sm2[0] * (1.0f / 1024.0f) - mean * mean;
    float rstd = rsqrtf(var + 1e-5f);
    float4 gv = *(const float4*)(lg + tid * 4);
    float4 bv = *(const float4*)(lb + tid * 4);
    float4 ov;
    ov.x = (xv.x - mean) * rstd * gv.x + bv.x;
    ov.y = (xv.y - mean) * rstd * gv.y + bv.y;
    ov.z = (xv.z - mean) * rstd * gv.z + bv.z;
    ov.w = (xv.w - mean) * rstd * gv.w + bv.w;
    *(float4*)(out + (size_t)row * 1024 + tid * 4) = ov;
}

// ---------------------------------------------------------------------------
// Launch
// ---------------------------------------------------------------------------
extern "C" void kernel_launch(void* const* d_in, const int* in_sizes, int n_in,
                              void* d_out, int out_size) {
    const float* k_in = (const float*)d_in[0];
    const float* q_in = (const float*)d_in[1];
    const float* wk   = (const float*)d_in[2];
    const float* bk   = (const float*)d_in[3];
    const float* wq   = (const float*)d_in[4];
    const float* bq   = (const float*)d_in[5];
    const float* wv   = (const float*)d_in[6];
    const float* bv   = (const float*)d_in[7];
    const float* wd   = (const float*)d_in[8];
    const float* bd   = (const float*)d_in[9];
    const float* lg   = (const float*)d_in[10];
    const float* lb   = (const float*)d_in[11];

    float* out  = (float*)d_out;
    float* attn = out + (size_t)B_ * S_ * D_;  // tuple order: (out, attn)

    const int attn_smem_bytes = ATTN_SMEM_FLOATS * 4;  // 54528 B
    cudaFuncSetAttribute(attn_kernel, cudaFuncAttributeMaxDynamicSharedMemorySize,
                         attn_smem_bytes);

    dim3 pgrid(MTOT / 128, D_ / 128);  // (32, 8)
    proj_gemm<<<pgrid, 256>>>(q_in, wq, bq, 0);   // g_qx
    proj_gemm<<<pgrid, 256>>>(k_in, wk, bk, 1);   // g_kx
    proj_gemm<<<pgrid, 256>>>(k_in, wv, bv, 2);   // g_vx (v = k)

    vcs_kernel<<<HB_, 256>>>();                   // V colsums

    attn_kernel<<<dim3(S_ / 64, HB_), 256, attn_smem_bytes>>>(attn);

    attn_norm<<<131072, 256>>>(attn);

    proj_gemm<<<pgrid, 256>>>(nullptr, wd, bd, 3);  // dense + relu -> g_dense
    ln_kernel<<<MTOT, 256>>>(lg, lb, out);
}

// round 8
// speedup vs baseline: 1.5494x; 1.2378x over previous
#include <cuda_runtime.h>
#include <cstdint>
#include <cstddef>

// Problem constants
#define B_    2
#define S_    2048
#define D_    1024
#define H_    16
#define DK_   64
#define MTOT  4096        // B_*S_
#define HB_   32          // H_*B_

// ---------------------------------------------------------------------------
// Scratch (static device allocations; no dynamic alloc allowed)
// ---------------------------------------------------------------------------
static __device__ float g_qx[B_ * H_ * S_ * DK_];   // [b][h][s][dk]
static __device__ float g_kx[B_ * H_ * S_ * DK_];
static __device__ float g_vx[B_ * H_ * S_ * DK_];
static __device__ float g_ctx[(size_t)MTOT * D_];   // [b*S+s][h*64+dk]
static __device__ float g_dense[(size_t)MTOT * D_];
static __device__ float g_rinv[HB_ * S_];           // 1/rowsum per attn row
static __device__ float g_vcs[HB_ * DK_];           // colsum of V per (b*H+h, d)

// ---------------------------------------------------------------------------
// Helpers
// ---------------------------------------------------------------------------
__device__ __forceinline__ float tf32_hi(float x) {
    uint32_t r;
    asm("cvt.rna.tf32.f32 %0, %1;" : "=r"(r) : "f"(x));
    return __uint_as_float(r);
}

__device__ __forceinline__ void mma_tf32(float c[4],
                                         uint32_t a0, uint32_t a1, uint32_t a2, uint32_t a3,
                                         uint32_t b0, uint32_t b1) {
    asm volatile(
        "mma.sync.aligned.m16n8k8.row.col.f32.tf32.tf32.f32 "
        "{%0,%1,%2,%3}, {%4,%5,%6,%7}, {%8,%9}, {%0,%1,%2,%3};\n"
        : "+f"(c[0]), "+f"(c[1]), "+f"(c[2]), "+f"(c[3])
        : "r"(a0), "r"(a1), "r"(a2), "r"(a3), "r"(b0), "r"(b1));
}

// ---------------------------------------------------------------------------
// QKV projection GEMM (1xTF32): C[4096x1024] = A @ W^T + bias, scatter to
// [b][h][s][dk].  mode 0/1/2 -> g_qx/g_kx/g_vx.
// BM=128 BN=128 BK=16, 256 threads, warps 2(m) x 4(n), warp tile 64x32.
// ---------------------------------------------------------------------------
__global__ __launch_bounds__(256) void qkv_gemm(const float* __restrict__ A,
                                                const float* __restrict__ W,
                                                const float* __restrict__ bias,
                                                int mode) {
    __shared__ float As[128 * 20];
    __shared__ float Bs[128 * 20];

    const int tid  = threadIdx.x;
    const int lane = tid & 31;
    const int warp = tid >> 5;
    const int wm   = warp & 1;
    const int wn   = warp >> 1;
    const int m0   = blockIdx.x * 128;
    const int n0   = blockIdx.y * 128;

    float c[4][4][4];
#pragma unroll
    for (int i = 0; i < 4; i++)
#pragma unroll
        for (int j = 0; j < 4; j++)
#pragma unroll
            for (int k = 0; k < 4; k++) c[i][j][k] = 0.f;

    for (int k0 = 0; k0 < 1024; k0 += 16) {
#pragma unroll
        for (int i = 0; i < 2; i++) {
            int lin = tid + i * 256;
            int r   = lin >> 2;
            int c4  = (lin & 3) * 4;
            float4 av = *(const float4*)(A + (size_t)(m0 + r) * 1024 + k0 + c4);
            av.x = tf32_hi(av.x); av.y = tf32_hi(av.y);
            av.z = tf32_hi(av.z); av.w = tf32_hi(av.w);
            *(float4*)(As + r * 20 + c4) = av;

            float4 bvv = *(const float4*)(W + (size_t)(n0 + r) * 1024 + k0 + c4);
            bvv.x = tf32_hi(bvv.x); bvv.y = tf32_hi(bvv.y);
            bvv.z = tf32_hi(bvv.z); bvv.w = tf32_hi(bvv.w);
            *(float4*)(Bs + r * 20 + c4) = bvv;
        }
        __syncthreads();

#pragma unroll
        for (int kg = 0; kg < 16; kg += 8) {
            uint32_t bh[4][2];
#pragma unroll
            for (int nt = 0; nt < 4; nt++) {
                int boff = (wn * 32 + nt * 8 + (lane >> 2)) * 20 + kg + (lane & 3);
                bh[nt][0] = __float_as_uint(Bs[boff]);
                bh[nt][1] = __float_as_uint(Bs[boff + 4]);
            }
#pragma unroll
            for (int mt = 0; mt < 4; mt++) {
                int aoff = (wm * 64 + mt * 16 + (lane >> 2)) * 20 + kg + (lane & 3);
                uint32_t a0 = __float_as_uint(As[aoff]);
                uint32_t a1 = __float_as_uint(As[aoff + 8 * 20]);
                uint32_t a2 = __float_as_uint(As[aoff + 4]);
                uint32_t a3 = __float_as_uint(As[aoff + 8 * 20 + 4]);
#pragma unroll
                for (int nt = 0; nt < 4; nt++)
                    mma_tf32(c[mt][nt], a0, a1, a2, a3, bh[nt][0], bh[nt][1]);
            }
        }
        __syncthreads();
    }

#pragma unroll
    for (int mt = 0; mt < 4; mt++) {
#pragma unroll
        for (int nt = 0; nt < 4; nt++) {
#pragma unroll
            for (int j = 0; j < 4; j++) {
                int row = m0 + wm * 64 + mt * 16 + (lane >> 2) + ((j >> 1) << 3);
                int col = n0 + wn * 32 + nt * 8 + 2 * (lane & 3) + (j & 1);
                float v = c[mt][nt][j] + bias[col];
                int b  = row >> 11;
                int s  = row & 2047;
                int h  = col >> 6;
                int dk = col & 63;
                float* dst = (mode == 0) ? g_qx : (mode == 1) ? g_kx : g_vx;
                dst[(((size_t)(b * H_ + h)) * S_ + s) * DK_ + dk] = v;
            }
        }
    }
}

// ---------------------------------------------------------------------------
// Dense GEMM (3xTF32, precision-critical path into `out`):
// g_dense = relu(g_ctx @ dense_w^T + dense_b)
// ---------------------------------------------------------------------------
__global__ __launch_bounds__(256) void dense_gemm(const float* __restrict__ W,
                                                  const float* __restrict__ bias) {
    __shared__ float As_h[128 * 20];
    __shared__ float As_l[128 * 20];
    __shared__ float Bs_h[128 * 20];
    __shared__ float Bs_l[128 * 20];

    const float* Ap = g_ctx;

    const int tid  = threadIdx.x;
    const int lane = tid & 31;
    const int warp = tid >> 5;
    const int wm   = warp & 1;
    const int wn   = warp >> 1;
    const int m0   = blockIdx.x * 128;
    const int n0   = blockIdx.y * 128;

    float c[4][4][4];
#pragma unroll
    for (int i = 0; i < 4; i++)
#pragma unroll
        for (int j = 0; j < 4; j++)
#pragma unroll
            for (int k = 0; k < 4; k++) c[i][j][k] = 0.f;

    for (int k0 = 0; k0 < 1024; k0 += 16) {
#pragma unroll
        for (int i = 0; i < 2; i++) {
            int lin = tid + i * 256;
            int r   = lin >> 2;
            int c4  = (lin & 3) * 4;
            float4 av = *(const float4*)(Ap + (size_t)(m0 + r) * 1024 + k0 + c4);
            float4 ah, al;
            ah.x = tf32_hi(av.x); al.x = av.x - ah.x;
            ah.y = tf32_hi(av.y); al.y = av.y - ah.y;
            ah.z = tf32_hi(av.z); al.z = av.z - ah.z;
            ah.w = tf32_hi(av.w); al.w = av.w - ah.w;
            *(float4*)(As_h + r * 20 + c4) = ah;
            *(float4*)(As_l + r * 20 + c4) = al;

            float4 bvv = *(const float4*)(W + (size_t)(n0 + r) * 1024 + k0 + c4);
            float4 bh, bl;
            bh.x = tf32_hi(bvv.x); bl.x = bvv.x - bh.x;
            bh.y = tf32_hi(bvv.y); bl.y = bvv.y - bh.y;
            bh.z = tf32_hi(bvv.z); bl.z = bvv.z - bh.z;
            bh.w = tf32_hi(bvv.w); bl.w = bvv.w - bh.w;
            *(float4*)(Bs_h + r * 20 + c4) = bh;
            *(float4*)(Bs_l + r * 20 + c4) = bl;
        }
        __syncthreads();

#pragma unroll
        for (int kg = 0; kg < 16; kg += 8) {
            uint32_t bh[4][2], bl[4][2];
#pragma unroll
            for (int nt = 0; nt < 4; nt++) {
                int boff = (wn * 32 + nt * 8 + (lane >> 2)) * 20 + kg + (lane & 3);
                bh[nt][0] = __float_as_uint(Bs_h[boff]);
                bh[nt][1] = __float_as_uint(Bs_h[boff + 4]);
                bl[nt][0] = __float_as_uint(Bs_l[boff]);
                bl[nt][1] = __float_as_uint(Bs_l[boff + 4]);
            }
#pragma unroll
            for (int mt = 0; mt < 4; mt++) {
                int aoff = (wm * 64 + mt * 16 + (lane >> 2)) * 20 + kg + (lane & 3);
                uint32_t ah0 = __float_as_uint(As_h[aoff]);
                uint32_t ah1 = __float_as_uint(As_h[aoff + 8 * 20]);
                uint32_t ah2 = __float_as_uint(As_h[aoff + 4]);
                uint32_t ah3 = __float_as_uint(As_h[aoff + 8 * 20 + 4]);
                uint32_t al0 = __float_as_uint(As_l[aoff]);
                uint32_t al1 = __float_as_uint(As_l[aoff + 8 * 20]);
                uint32_t al2 = __float_as_uint(As_l[aoff + 4]);
                uint32_t al3 = __float_as_uint(As_l[aoff + 8 * 20 + 4]);
#pragma unroll
                for (int nt = 0; nt < 4; nt++) {
                    mma_tf32(c[mt][nt], ah0, ah1, ah2, ah3, bh[nt][0], bh[nt][1]);
                    mma_tf32(c[mt][nt], ah0, ah1, ah2, ah3, bl[nt][0], bl[nt][1]);
                    mma_tf32(c[mt][nt], al0, al1, al2, al3, bh[nt][0], bh[nt][1]);
                }
            }
        }
        __syncthreads();
    }

#pragma unroll
    for (int mt = 0; mt < 4; mt++) {
#pragma unroll
        for (int nt = 0; nt < 4; nt++) {
#pragma unroll
            for (int j = 0; j < 4; j++) {
                int row = m0 + wm * 64 + mt * 16 + (lane >> 2) + ((j >> 1) << 3);
                int col = n0 + wn * 32 + nt * 8 + 2 * (lane & 3) + (j & 1);
                float v = c[mt][nt][j] + bias[col];
                g_dense[(size_t)row * 1024 + col] = v > 0.f ? v : 0.f;
            }
        }
    }
}

// ---------------------------------------------------------------------------
// V column-sum per (b*H+h, d):  g_vcs[bh][d] = sum_s g_vx[bh][s][d]
// ---------------------------------------------------------------------------
__global__ __launch_bounds__(256) void vcs_kernel() {
    const int bh = blockIdx.x;
    const float* vb = g_vx + (size_t)bh * S_ * DK_;
    const int d = threadIdx.x & 63;
    const int c = threadIdx.x >> 6;   // 0..3
    float s = 0.f;
    for (int r = c * 512; r < (c + 1) * 512; r++) s += vb[(size_t)r * 64 + d];
    __shared__ float sm[256];
    sm[threadIdx.x] = s;
    __syncthreads();
    if (threadIdx.x < 64)
        g_vcs[bh * 64 + threadIdx.x] =
            sm[threadIdx.x] + sm[threadIdx.x + 64] + sm[threadIdx.x + 128] + sm[threadIdx.x + 192];
}

// ---------------------------------------------------------------------------
// Fused attention kernel (v2, smem-traffic-minimized).
// grid = (S/64, H*B), block = 256 (8 warps: wm in 0..3 = q-rows, wn in 0..1 = k-half)
// ---------------------------------------------------------------------------
#define KSTR 68
#define VSTR 72
#define PSTR 36
#define OSTR 66
#define ATTN_SMEM_FLOATS (64 * KSTR + 64 * VSTR + 8 * 16 * PSTR + 64)

__global__ __launch_bounds__(256, 2) void attn_kernel(float* __restrict__ attn_out) {
    extern __shared__ float smf[];
    float* Kh   = smf;                       // 64 x 68 (tf32-rounded K)
    float* Vs   = Kh + 64 * KSTR;            // 64 x 72 (raw V)
    float* Pb   = Vs + 64 * VSTR;            // 8 warps x 16 x 36 (dp buffer)
    float* rs   = Pb + 8 * 16 * PSTR;        // rowsum[64]
    float* Obuf = smf;                       // epilogue alias: 2 x 64 x 66

    const int tid  = threadIdx.x;
    const int lane = tid & 31;
    const int warp = tid >> 5;
    const int wm   = warp & 3;               // q-row group
    const int wn   = warp >> 2;              // k half
    const int g    = lane >> 2;
    const int j    = lane & 3;
    const int hb   = blockIdx.y;             // h*B + b
    const int h    = hb >> 1;
    const int b    = hb & 1;
    const int q0   = blockIdx.x * 64;

    const float* qbase = g_qx + ((size_t)(b * H_ + h)) * S_ * DK_;
    const float* kbase = g_kx + ((size_t)(b * H_ + h)) * S_ * DK_;
    const float* vbase = g_vx + ((size_t)(b * H_ + h)) * S_ * DK_;
    const float invT = 0.03125f;             // 1/sqrt(1024)

    if (tid < 64) rs[tid] = 0.f;

    // Q fragments in registers: rows (wm*16+g, +8), cols kg*8+j, +4; pre-scaled
    uint32_t qa[8][4];
    {
        const float* qr0 = qbase + (size_t)(q0 + wm * 16 + g) * 64;
        const float* qr1 = qr0 + 8 * 64;
#pragma unroll
        for (int kg = 0; kg < 8; kg++) {
            qa[kg][0] = __float_as_uint(tf32_hi(qr0[kg * 8 + j] * invT));
            qa[kg][1] = __float_as_uint(tf32_hi(qr1[kg * 8 + j] * invT));
            qa[kg][2] = __float_as_uint(tf32_hi(qr0[kg * 8 + j + 4] * invT));
            qa[kg][3] = __float_as_uint(tf32_hi(qr1[kg * 8 + j + 4] * invT));
        }
    }

    float o[8][4];
#pragma unroll
    for (int i = 0; i < 8; i++)
#pragma unroll
        for (int k = 0; k < 4; k++) o[i][k] = 0.f;
    float rs0 = 0.f, rs1 = 0.f;
    float* Pw = Pb + warp * 16 * PSTR;

    for (int kt = 0; kt < 32; kt++) {
        const int k0 = kt * 64;
        // stage K (tf32) and V (raw)
#pragma unroll
        for (int i = 0; i < 4; i++) {
            int lin = tid + i * 256;
            int r   = lin >> 4;
            int c4  = (lin & 15) * 4;
            float4 kv = *(const float4*)(kbase + (size_t)(k0 + r) * 64 + c4);
            float4 ko;
            ko.x = tf32_hi(kv.x); ko.y = tf32_hi(kv.y);
            ko.z = tf32_hi(kv.z); ko.w = tf32_hi(kv.w);
            *(float4*)(Kh + r * KSTR + c4) = ko;
            *(float4*)(Vs + r * VSTR + c4) =
                *(const float4*)(vbase + (size_t)(k0 + r) * 64 + c4);
        }
        __syncthreads();

        // scores: 16 q-rows x 32 kv (this warp's half)
        float s[4][4];
#pragma unroll
        for (int i = 0; i < 4; i++)
#pragma unroll
            for (int k = 0; k < 4; k++) s[i][k] = 0.f;
#pragma unroll
        for (int kg = 0; kg < 8; kg++) {
#pragma unroll
            for (int nt = 0; nt < 4; nt++) {
                int boff = (wn * 32 + nt * 8 + g) * KSTR + kg * 8 + j;
                mma_tf32(s[nt], qa[kg][0], qa[kg][1], qa[kg][2], qa[kg][3],
                         __float_as_uint(Kh[boff]), __float_as_uint(Kh[boff + 4]));
            }
        }

        // exp -> gmem attn (unnormalized), rowsum regs, dp -> warp smem buffer
        float* ab = attn_out + ((size_t)hb * S_ + q0 + wm * 16 + g) * S_ + k0 + wn * 32;
#pragma unroll
        for (int nt = 0; nt < 4; nt++) {
            float p0 = __expf(s[nt][0]);
            float p1 = __expf(s[nt][1]);
            float p2 = __expf(s[nt][2]);
            float p3 = __expf(s[nt][3]);
            rs0 += p0 + p1;
            rs1 += p2 + p3;
            *(float2*)(ab + nt * 8 + 2 * j) = make_float2(p0, p1);
            *(float2*)(ab + (size_t)8 * S_ + nt * 8 + 2 * j) = make_float2(p2, p3);
            *(float2*)(Pw + g * PSTR + nt * 8 + 2 * j)       = make_float2(p0 - 1.f, p1 - 1.f);
            *(float2*)(Pw + (g + 8) * PSTR + nt * 8 + 2 * j) = make_float2(p2 - 1.f, p3 - 1.f);
        }
        __syncwarp();

        // O_half += dp @ V over this warp's 32-k half
#pragma unroll
        for (int kp = 0; kp < 4; kp++) {
            uint32_t a0 = __float_as_uint(Pw[g * PSTR + kp * 8 + j]);
            uint32_t a1 = __float_as_uint(Pw[(g + 8) * PSTR + kp * 8 + j]);
            uint32_t a2 = __float_as_uint(Pw[g * PSTR + kp * 8 + j + 4]);
            uint32_t a3 = __float_as_uint(Pw[(g + 8) * PSTR + kp * 8 + j + 4]);
#pragma unroll
            for (int nv = 0; nv < 8; nv++) {
                int boff = (wn * 32 + kp * 8 + j) * VSTR + nv * 8 + g;
                mma_tf32(o[nv], a0, a1, a2, a3,
                         __float_as_uint(Vs[boff]), __float_as_uint(Vs[boff + 4 * VSTR]));
            }
        }
        __syncthreads();
    }

    // --- epilogue ---
    float* Ob = Obuf + wn * 64 * OSTR + (wm * 16) * OSTR;
#pragma unroll
    for (int nv = 0; nv < 8; nv++) {
        *(float2*)(Ob + g * OSTR + nv * 8 + 2 * j)       = make_float2(o[nv][0], o[nv][1]);
        *(float2*)(Ob + (g + 8) * OSTR + nv * 8 + 2 * j) = make_float2(o[nv][2], o[nv][3]);
    }
    rs0 += __shfl_xor_sync(0xffffffffu, rs0, 1);
    rs0 += __shfl_xor_sync(0xffffffffu, rs0, 2);
    rs1 += __shfl_xor_sync(0xffffffffu, rs1, 1);
    rs1 += __shfl_xor_sync(0xffffffffu, rs1, 2);
    if (j == 0) {
        atomicAdd(&rs[wm * 16 + g], rs0);
        atomicAdd(&rs[wm * 16 + 8 + g], rs1);
    }
    __syncthreads();
    if (tid < 64) {
        float inv = 1.0f / rs[tid];
        g_rinv[(size_t)hb * S_ + q0 + tid] = inv;
        rs[tid] = inv;
    }
    __syncthreads();

    const float* vc = g_vcs + (b * H_ + h) * 64;
#pragma unroll
    for (int i = 0; i < 16; i++) {
        int lin = tid + i * 256;
        int qr  = lin >> 6;
        int d   = lin & 63;
        float val = (Obuf[qr * OSTR + d] + Obuf[64 * OSTR + qr * OSTR + d] + vc[d]) * rs[qr];
        g_ctx[((size_t)(b * S_ + q0 + qr)) * D_ + h * 64 + d] = val;
    }
}

// ---------------------------------------------------------------------------
// Normalize attn in place: attn[hb][q][k] *= g_rinv[hb*S+q]
// ---------------------------------------------------------------------------
__global__ __launch_bounds__(256) void attn_norm(float* __restrict__ attn) {
    size_t i = (size_t)blockIdx.x * 256 + threadIdx.x;  // float4 index
    float inv = g_rinv[i >> 9];                          // 512 float4 per row
    float4* p = (float4*)attn;
    float4 v = p[i];
    v.x *= inv; v.y *= inv; v.z *= inv; v.w *= inv;
    p[i] = v;
}

// ---------------------------------------------------------------------------
// LayerNorm over rows of g_dense -> out
// ---------------------------------------------------------------------------
__global__ __launch_bounds__(256) void ln_kernel(const float* __restrict__ lg,
                                                 const float* __restrict__ lb,
                                                 float* __restrict__ out) {
    const int row = blockIdx.x;
    const int tid = threadIdx.x;
    const float* x = g_dense + (size_t)row * 1024;
    float4 xv = *(const float4*)(x + tid * 4);
    float s  = xv.x + xv.y + xv.z + xv.w;
    float ss = fmaf(xv.x, xv.x, fmaf(xv.y, xv.y, fmaf(xv.z, xv.z, xv.w * xv.w)));
#pragma unroll
    for (int off = 16; off > 0; off >>= 1) {
        s  += __shfl_xor_sync(0xffffffffu, s, off);
        ss += __shfl_xor_sync(0xffffffffu, ss, off);
    }
    __shared__ float sm1[8], sm2[8];
    if ((tid & 31) == 0) { sm1[tid >> 5] = s; sm2[tid >> 5] = ss; }
    __syncthreads();
    if (tid < 32) {
        float a  = (tid < 8) ? sm1[tid] : 0.f;
        float b2 = (tid < 8) ? sm2[tid] : 0.f;
#pragma unroll
        for (int off = 4; off > 0; off >>= 1) {
            a  += __shfl_xor_sync(0xffffffffu, a, off);
            b2 += __shfl_xor_sync(0xffffffffu, b2, off);
        }
        if (tid == 0) { sm1[0] = a; sm2[0] = b2; }
    }
    __syncthreads();
    float mean = sm1[0] * (1.0f / 1024.0f);
    float var  = sm2[0] * (1.0f / 1024.0f) - mean * mean;
    float rstd = rsqrtf(var + 1e-5f);
    float4 gv = *(const float4*)(lg + tid * 4);
    float4 bv = *(const float4*)(lb + tid * 4);
    float4 ov;
    ov.x = (xv.x - mean) * rstd * gv.x + bv.x;
    ov.y = (xv.y - mean) * rstd * gv.y + bv.y;
    ov.z = (xv.z - mean) * rstd * gv.z + bv.z;
    ov.w = (xv.w - mean) * rstd * gv.w + bv.w;
    *(float4*)(out + (size_t)row * 1024 + tid * 4) = ov;
}

// ---------------------------------------------------------------------------
// Launch
// ---------------------------------------------------------------------------
extern "C" void kernel_launch(void* const* d_in, const int* in_sizes, int n_in,
                              void* d_out, int out_size) {
    const float* k_in = (const float*)d_in[0];
    const float* q_in = (const float*)d_in[1];
    const float* wk   = (const float*)d_in[2];
    const float* bk   = (const float*)d_in[3];
    const float* wq   = (const float*)d_in[4];
    const float* bq   = (const float*)d_in[5];
    const float* wv   = (const float*)d_in[6];
    const float* bv   = (const float*)d_in[7];
    const float* wd   = (const float*)d_in[8];
    const float* bd   = (const float*)d_in[9];
    const float* lg   = (const float*)d_in[10];
    const float* lb   = (const float*)d_in[11];

    float* out  = (float*)d_out;
    float* attn = out + (size_t)B_ * S_ * D_;  // tuple order: (out, attn)

    const int attn_smem_bytes = ATTN_SMEM_FLOATS * 4;  // 54528 B
    cudaFuncSetAttribute(attn_kernel, cudaFuncAttributeMaxDynamicSharedMemorySize,
                         attn_smem_bytes);

    dim3 pgrid(MTOT / 128, D_ / 128);  // (32, 8)
    qkv_gemm<<<pgrid, 256>>>(q_in, wq, bq, 0);   // g_qx
    qkv_gemm<<<pgrid, 256>>>(k_in, wk, bk, 1);   // g_kx
    qkv_gemm<<<pgrid, 256>>>(k_in, wv, bv, 2);   // g_vx (v = k)

    vcs_kernel<<<HB_, 256>>>();                  // V colsums

    attn_kernel<<<dim3(S_ / 64, HB_), 256, attn_smem_bytes>>>(attn);

    attn_norm<<<131072, 256>>>(attn);

    dense_gemm<<<pgrid, 256>>>(wd, bd);          // dense + relu -> g_dense
    ln_kernel<<<MTOT, 256>>>(lg, lb, out);
}

// round 9
// speedup vs baseline: 1.7166x; 1.1079x over previous
#include <cuda_runtime.h>
#include <cstdint>
#include <cstddef>

// Problem constants
#define B_    2
#define S_    2048
#define D_    1024
#define H_    16
#define DK_   64
#define MTOT  4096        // B_*S_
#define HB_   32          // H_*B_

// ---------------------------------------------------------------------------
// Scratch (static device allocations; no dynamic alloc allowed)
// ---------------------------------------------------------------------------
static __device__ float g_qx[B_ * H_ * S_ * DK_];   // [b][h][s][dk]
static __device__ float g_kx[B_ * H_ * S_ * DK_];
static __device__ float g_vx[B_ * H_ * S_ * DK_];
static __device__ float g_ctx[(size_t)MTOT * D_];   // [b*S+s][h*64+dk]
static __device__ float g_dense[(size_t)MTOT * D_];
static __device__ float g_rinv[HB_ * S_];           // 1/rowsum per attn row
static __device__ float g_vcs[HB_ * DK_];           // colsum of V per (b*H+h, d)

// ---------------------------------------------------------------------------
// Helpers
// ---------------------------------------------------------------------------
__device__ __forceinline__ float tf32_hi(float x) {
    uint32_t r;
    asm("cvt.rna.tf32.f32 %0, %1;" : "=r"(r) : "f"(x));
    return __uint_as_float(r);
}

__device__ __forceinline__ void mma_tf32(float c[4],
                                         uint32_t a0, uint32_t a1, uint32_t a2, uint32_t a3,
                                         uint32_t b0, uint32_t b1) {
    asm volatile(
        "mma.sync.aligned.m16n8k8.row.col.f32.tf32.tf32.f32 "
        "{%0,%1,%2,%3}, {%4,%5,%6,%7}, {%8,%9}, {%0,%1,%2,%3};\n"
        : "+f"(c[0]), "+f"(c[1]), "+f"(c[2]), "+f"(c[3])
        : "r"(a0), "r"(a1), "r"(a2), "r"(a3), "r"(b0), "r"(b1));
}

__device__ __forceinline__ void cp_async16(uint32_t smem_addr, const void* gptr) {
    asm volatile("cp.async.cg.shared.global [%0], [%1], 16;"
                 :: "r"(smem_addr), "l"(gptr));
}

// ---------------------------------------------------------------------------
// QKV projection GEMM (1xTF32): C[4096x1024] = A @ W^T + bias, scatter to
// [b][h][s][dk].  mode 0/1/2 -> g_qx/g_kx/g_vx.
// ---------------------------------------------------------------------------
__global__ __launch_bounds__(256) void qkv_gemm(const float* __restrict__ A,
                                                const float* __restrict__ W,
                                                const float* __restrict__ bias,
                                                int mode) {
    __shared__ float As[128 * 20];
    __shared__ float Bs[128 * 20];

    const int tid  = threadIdx.x;
    const int lane = tid & 31;
    const int warp = tid >> 5;
    const int wm   = warp & 1;
    const int wn   = warp >> 1;
    const int m0   = blockIdx.x * 128;
    const int n0   = blockIdx.y * 128;

    float c[4][4][4];
#pragma unroll
    for (int i = 0; i < 4; i++)
#pragma unroll
        for (int j = 0; j < 4; j++)
#pragma unroll
            for (int k = 0; k < 4; k++) c[i][j][k] = 0.f;

    for (int k0 = 0; k0 < 1024; k0 += 16) {
#pragma unroll
        for (int i = 0; i < 2; i++) {
            int lin = tid + i * 256;
            int r   = lin >> 2;
            int c4  = (lin & 3) * 4;
            float4 av = *(const float4*)(A + (size_t)(m0 + r) * 1024 + k0 + c4);
            av.x = tf32_hi(av.x); av.y = tf32_hi(av.y);
            av.z = tf32_hi(av.z); av.w = tf32_hi(av.w);
            *(float4*)(As + r * 20 + c4) = av;

            float4 bvv = *(const float4*)(W + (size_t)(n0 + r) * 1024 + k0 + c4);
            bvv.x = tf32_hi(bvv.x); bvv.y = tf32_hi(bvv.y);
            bvv.z = tf32_hi(bvv.z); bvv.w = tf32_hi(bvv.w);
            *(float4*)(Bs + r * 20 + c4) = bvv;
        }
        __syncthreads();

#pragma unroll
        for (int kg = 0; kg < 16; kg += 8) {
            uint32_t bh[4][2];
#pragma unroll
            for (int nt = 0; nt < 4; nt++) {
                int boff = (wn * 32 + nt * 8 + (lane >> 2)) * 20 + kg + (lane & 3);
                bh[nt][0] = __float_as_uint(Bs[boff]);
                bh[nt][1] = __float_as_uint(Bs[boff + 4]);
            }
#pragma unroll
            for (int mt = 0; mt < 4; mt++) {
                int aoff = (wm * 64 + mt * 16 + (lane >> 2)) * 20 + kg + (lane & 3);
                uint32_t a0 = __float_as_uint(As[aoff]);
                uint32_t a1 = __float_as_uint(As[aoff + 8 * 20]);
                uint32_t a2 = __float_as_uint(As[aoff + 4]);
                uint32_t a3 = __float_as_uint(As[aoff + 8 * 20 + 4]);
#pragma unroll
                for (int nt = 0; nt < 4; nt++)
                    mma_tf32(c[mt][nt], a0, a1, a2, a3, bh[nt][0], bh[nt][1]);
            }
        }
        __syncthreads();
    }

#pragma unroll
    for (int mt = 0; mt < 4; mt++) {
#pragma unroll
        for (int nt = 0; nt < 4; nt++) {
#pragma unroll
            for (int j = 0; j < 4; j++) {
                int row = m0 + wm * 64 + mt * 16 + (lane >> 2) + ((j >> 1) << 3);
                int col = n0 + wn * 32 + nt * 8 + 2 * (lane & 3) + (j & 1);
                float v = c[mt][nt][j] + bias[col];
                int b  = row >> 11;
                int s  = row & 2047;
                int h  = col >> 6;
                int dk = col & 63;
                float* dst = (mode == 0) ? g_qx : (mode == 1) ? g_kx : g_vx;
                dst[(((size_t)(b * H_ + h)) * S_ + s) * DK_ + dk] = v;
            }
        }
    }
}

// ---------------------------------------------------------------------------
// Dense GEMM (3xTF32, precision-critical path into `out`):
// g_dense = relu(g_ctx @ dense_w^T + dense_b)
// ---------------------------------------------------------------------------
__global__ __launch_bounds__(256) void dense_gemm(const float* __restrict__ W,
                                                  const float* __restrict__ bias) {
    __shared__ float As_h[128 * 20];
    __shared__ float As_l[128 * 20];
    __shared__ float Bs_h[128 * 20];
    __shared__ float Bs_l[128 * 20];

    const float* Ap = g_ctx;

    const int tid  = threadIdx.x;
    const int lane = tid & 31;
    const int warp = tid >> 5;
    const int wm   = warp & 1;
    const int wn   = warp >> 1;
    const int m0   = blockIdx.x * 128;
    const int n0   = blockIdx.y * 128;

    float c[4][4][4];
#pragma unroll
    for (int i = 0; i < 4; i++)
#pragma unroll
        for (int j = 0; j < 4; j++)
#pragma unroll
            for (int k = 0; k < 4; k++) c[i][j][k] = 0.f;

    for (int k0 = 0; k0 < 1024; k0 += 16) {
#pragma unroll
        for (int i = 0; i < 2; i++) {
            int lin = tid + i * 256;
            int r   = lin >> 2;
            int c4  = (lin & 3) * 4;
            float4 av = *(const float4*)(Ap + (size_t)(m0 + r) * 1024 + k0 + c4);
            float4 ah, al;
            ah.x = tf32_hi(av.x); al.x = av.x - ah.x;
            ah.y = tf32_hi(av.y); al.y = av.y - ah.y;
            ah.z = tf32_hi(av.z); al.z = av.z - ah.z;
            ah.w = tf32_hi(av.w); al.w = av.w - ah.w;
            *(float4*)(As_h + r * 20 + c4) = ah;
            *(float4*)(As_l + r * 20 + c4) = al;

            float4 bvv = *(const float4*)(W + (size_t)(n0 + r) * 1024 + k0 + c4);
            float4 bh, bl;
            bh.x = tf32_hi(bvv.x); bl.x = bvv.x - bh.x;
            bh.y = tf32_hi(bvv.y); bl.y = bvv.y - bh.y;
            bh.z = tf32_hi(bvv.z); bl.z = bvv.z - bh.z;
            bh.w = tf32_hi(bvv.w); bl.w = bvv.w - bh.w;
            *(float4*)(Bs_h + r * 20 + c4) = bh;
            *(float4*)(Bs_l + r * 20 + c4) = bl;
        }
        __syncthreads();

#pragma unroll
        for (int kg = 0; kg < 16; kg += 8) {
            uint32_t bh[4][2], bl[4][2];
#pragma unroll
            for (int nt = 0; nt < 4; nt++) {
                int boff = (wn * 32 + nt * 8 + (lane >> 2)) * 20 + kg + (lane & 3);
                bh[nt][0] = __float_as_uint(Bs_h[boff]);
                bh[nt][1] = __float_as_uint(Bs_h[boff + 4]);
                bl[nt][0] = __float_as_uint(Bs_l[boff]);
                bl[nt][1] = __float_as_uint(Bs_l[boff + 4]);
            }
#pragma unroll
            for (int mt = 0; mt < 4; mt++) {
                int aoff = (wm * 64 + mt * 16 + (lane >> 2)) * 20 + kg + (lane & 3);
                uint32_t ah0 = __float_as_uint(As_h[aoff]);
                uint32_t ah1 = __float_as_uint(As_h[aoff + 8 * 20]);
                uint32_t ah2 = __float_as_uint(As_h[aoff + 4]);
                uint32_t ah3 = __float_as_uint(As_h[aoff + 8 * 20 + 4]);
                uint32_t al0 = __float_as_uint(As_l[aoff]);
                uint32_t al1 = __float_as_uint(As_l[aoff + 8 * 20]);
                uint32_t al2 = __float_as_uint(As_l[aoff + 4]);
                uint32_t al3 = __float_as_uint(As_l[aoff + 8 * 20 + 4]);
#pragma unroll
                for (int nt = 0; nt < 4; nt++) {
                    mma_tf32(c[mt][nt], ah0, ah1, ah2, ah3, bh[nt][0], bh[nt][1]);
                    mma_tf32(c[mt][nt], ah0, ah1, ah2, ah3, bl[nt][0], bl[nt][1]);
                    mma_tf32(c[mt][nt], al0, al1, al2, al3, bh[nt][0], bh[nt][1]);
                }
            }
        }
        __syncthreads();
    }

#pragma unroll
    for (int mt = 0; mt < 4; mt++) {
#pragma unroll
        for (int nt = 0; nt < 4; nt++) {
#pragma unroll
            for (int j = 0; j < 4; j++) {
                int row = m0 + wm * 64 + mt * 16 + (lane >> 2) + ((j >> 1) << 3);
                int col = n0 + wn * 32 + nt * 8 + 2 * (lane & 3) + (j & 1);
                float v = c[mt][nt][j] + bias[col];
                g_dense[(size_t)row * 1024 + col] = v > 0.f ? v : 0.f;
            }
        }
    }
}

// ---------------------------------------------------------------------------
// V column-sum per (b*H+h, d):  g_vcs[bh][d] = sum_s g_vx[bh][s][d]
// ---------------------------------------------------------------------------
__global__ __launch_bounds__(256) void vcs_kernel() {
    const int bh = blockIdx.x;
    const float* vb = g_vx + (size_t)bh * S_ * DK_;
    const int d = threadIdx.x & 63;
    const int c = threadIdx.x >> 6;   // 0..3
    float s = 0.f;
    for (int r = c * 512; r < (c + 1) * 512; r++) s += vb[(size_t)r * 64 + d];
    __shared__ float sm[256];
    sm[threadIdx.x] = s;
    __syncthreads();
    if (threadIdx.x < 64)
        g_vcs[bh * 64 + threadIdx.x] =
            sm[threadIdx.x] + sm[threadIdx.x + 64] + sm[threadIdx.x + 128] + sm[threadIdx.x + 192];
}

// ---------------------------------------------------------------------------
// Fused attention kernel (v3: cp.async double-buffered K/V pipeline).
// grid = (S/64, H*B), block = 256 (8 warps: wm 0..3 = q-rows, wn 0..1 = k-half)
// K staged RAW (MMA truncates to tf32 — bias ~3e-5 on attn, acceptable).
// ---------------------------------------------------------------------------
#define KSTR 68
#define VSTR 72
#define KVBUF (64 * KSTR + 64 * VSTR)   // 8960 floats per buffer
#define PSTR 36
#define OSTR 66
#define ATTN_SMEM_FLOATS (2 * KVBUF + 8 * 16 * PSTR + 64)   // 22592 floats = 90368 B

__global__ __launch_bounds__(256, 2) void attn_kernel(float* __restrict__ attn_out) {
    extern __shared__ float smf[];
    float* Pb   = smf + 2 * KVBUF;           // 8 warps x 16 x 36 (dp buffer)
    float* rs   = Pb + 8 * 16 * PSTR;        // rowsum[64]
    float* Obuf = smf;                       // epilogue alias: 2 x 64 x 66 (8448 <= 17920)

    const int tid  = threadIdx.x;
    const int lane = tid & 31;
    const int warp = tid >> 5;
    const int wm   = warp & 3;               // q-row group
    const int wn   = warp >> 2;              // k half
    const int g    = lane >> 2;
    const int j    = lane & 3;
    const int hb   = blockIdx.y;             // h*B + b
    const int h    = hb >> 1;
    const int b    = hb & 1;
    const int q0   = blockIdx.x * 64;

    const float* qbase = g_qx + ((size_t)(b * H_ + h)) * S_ * DK_;
    const float* kbase = g_kx + ((size_t)(b * H_ + h)) * S_ * DK_;
    const float* vbase = g_vx + ((size_t)(b * H_ + h)) * S_ * DK_;
    const float invT = 0.03125f;             // 1/sqrt(1024)

    if (tid < 64) rs[tid] = 0.f;

    // staging thread coords (each thread moves 4 16B chunks of K and 4 of V)
    const int sr  = tid >> 4;                // base row 0..15 (+16 per i)
    const int sc4 = (tid & 15) * 4;          // col 0..60

    // prologue: issue tile 0 loads
    {
        float* Kb = smf;
        float* Vb = smf + 64 * KSTR;
        uint32_t ksm = (uint32_t)__cvta_generic_to_shared(Kb);
        uint32_t vsm = (uint32_t)__cvta_generic_to_shared(Vb);
#pragma unroll
        for (int i = 0; i < 4; i++) {
            int r = sr + i * 16;
            cp_async16(ksm + (r * KSTR + sc4) * 4, kbase + (size_t)r * 64 + sc4);
            cp_async16(vsm + (r * VSTR + sc4) * 4, vbase + (size_t)r * 64 + sc4);
        }
        asm volatile("cp.async.commit_group;");
    }

    // Q fragments in registers: rows (wm*16+g, +8), cols kg*8+j, +4; pre-scaled
    uint32_t qa[8][4];
    {
        const float* qr0 = qbase + (size_t)(q0 + wm * 16 + g) * 64;
        const float* qr1 = qr0 + 8 * 64;
#pragma unroll
        for (int kg = 0; kg < 8; kg++) {
            qa[kg][0] = __float_as_uint(tf32_hi(qr0[kg * 8 + j] * invT));
            qa[kg][1] = __float_as_uint(tf32_hi(qr1[kg * 8 + j] * invT));
            qa[kg][2] = __float_as_uint(tf32_hi(qr0[kg * 8 + j + 4] * invT));
            qa[kg][3] = __float_as_uint(tf32_hi(qr1[kg * 8 + j + 4] * invT));
        }
    }

    float o[8][4];
#pragma unroll
    for (int i = 0; i < 8; i++)
#pragma unroll
        for (int k = 0; k < 4; k++) o[i][k] = 0.f;
    float rs0 = 0.f, rs1 = 0.f;
    float* Pw = Pb + warp * 16 * PSTR;

    for (int kt = 0; kt < 32; kt++) {
        float* Kb = smf + (kt & 1) * KVBUF;
        float* Vb = Kb + 64 * KSTR;

        // wait for this tile's K/V, then all warps aligned
        asm volatile("cp.async.wait_group 0;");
        __syncthreads();

        // issue next tile's loads into the other buffer
        if (kt + 1 < 32) {
            float* Kn = smf + ((kt + 1) & 1) * KVBUF;
            float* Vn = Kn + 64 * KSTR;
            uint32_t ksm = (uint32_t)__cvta_generic_to_shared(Kn);
            uint32_t vsm = (uint32_t)__cvta_generic_to_shared(Vn);
            const float* kb = kbase + (size_t)(kt + 1) * 64 * 64;
            const float* vb = vbase + (size_t)(kt + 1) * 64 * 64;
#pragma unroll
            for (int i = 0; i < 4; i++) {
                int r = sr + i * 16;
                cp_async16(ksm + (r * KSTR + sc4) * 4, kb + (size_t)r * 64 + sc4);
                cp_async16(vsm + (r * VSTR + sc4) * 4, vb + (size_t)r * 64 + sc4);
            }
            asm volatile("cp.async.commit_group;");
        }

        // scores: 16 q-rows x 32 kv (this warp's half); K raw (tf32-truncated)
        float s[4][4];
#pragma unroll
        for (int i = 0; i < 4; i++)
#pragma unroll
            for (int k = 0; k < 4; k++) s[i][k] = 0.f;
#pragma unroll
        for (int kg = 0; kg < 8; kg++) {
#pragma unroll
            for (int nt = 0; nt < 4; nt++) {
                int boff = (wn * 32 + nt * 8 + g) * KSTR + kg * 8 + j;
                mma_tf32(s[nt], qa[kg][0], qa[kg][1], qa[kg][2], qa[kg][3],
                         __float_as_uint(Kb[boff]), __float_as_uint(Kb[boff + 4]));
            }
        }

        // exp -> gmem attn (unnormalized), rowsum regs, dp -> warp smem buffer
        const int k0 = kt * 64;
        float* ab = attn_out + ((size_t)hb * S_ + q0 + wm * 16 + g) * S_ + k0 + wn * 32;
#pragma unroll
        for (int nt = 0; nt < 4; nt++) {
            float p0 = __expf(s[nt][0]);
            float p1 = __expf(s[nt][1]);
            float p2 = __expf(s[nt][2]);
            float p3 = __expf(s[nt][3]);
            rs0 += p0 + p1;
            rs1 += p2 + p3;
            *(float2*)(ab + nt * 8 + 2 * j) = make_float2(p0, p1);
            *(float2*)(ab + (size_t)8 * S_ + nt * 8 + 2 * j) = make_float2(p2, p3);
            *(float2*)(Pw + g * PSTR + nt * 8 + 2 * j)       = make_float2(p0 - 1.f, p1 - 1.f);
            *(float2*)(Pw + (g + 8) * PSTR + nt * 8 + 2 * j) = make_float2(p2 - 1.f, p3 - 1.f);
        }
        __syncwarp();

        // O_half += dp @ V over this warp's 32-k half
#pragma unroll
        for (int kp = 0; kp < 4; kp++) {
            uint32_t a0 = __float_as_uint(Pw[g * PSTR + kp * 8 + j]);
            uint32_t a1 = __float_as_uint(Pw[(g + 8) * PSTR + kp * 8 + j]);
            uint32_t a2 = __float_as_uint(Pw[g * PSTR + kp * 8 + j + 4]);
            uint32_t a3 = __float_as_uint(Pw[(g + 8) * PSTR + kp * 8 + j + 4]);
#pragma unroll
            for (int nv = 0; nv < 8; nv++) {
                int boff = (wn * 32 + kp * 8 + j) * VSTR + nv * 8 + g;
                mma_tf32(o[nv], a0, a1, a2, a3,
                         __float_as_uint(Vb[boff]), __float_as_uint(Vb[boff + 4 * VSTR]));
            }
        }
    }

    // --- epilogue ---
    __syncthreads();   // all PV reads of the KV buffers complete before aliasing
    float* Ob = Obuf + wn * 64 * OSTR + (wm * 16) * OSTR;
#pragma unroll
    for (int nv = 0; nv < 8; nv++) {
        *(float2*)(Ob + g * OSTR + nv * 8 + 2 * j)       = make_float2(o[nv][0], o[nv][1]);
        *(float2*)(Ob + (g + 8) * OSTR + nv * 8 + 2 * j) = make_float2(o[nv][2], o[nv][3]);
    }
    rs0 += __shfl_xor_sync(0xffffffffu, rs0, 1);
    rs0 += __shfl_xor_sync(0xffffffffu, rs0, 2);
    rs1 += __shfl_xor_sync(0xffffffffu, rs1, 1);
    rs1 += __shfl_xor_sync(0xffffffffu, rs1, 2);
    if (j == 0) {
        atomicAdd(&rs[wm * 16 + g], rs0);
        atomicAdd(&rs[wm * 16 + 8 + g], rs1);
    }
    __syncthreads();
    if (tid < 64) {
        float inv = 1.0f / rs[tid];
        g_rinv[(size_t)hb * S_ + q0 + tid] = inv;
        rs[tid] = inv;
    }
    __syncthreads();

    const float* vc = g_vcs + (b * H_ + h) * 64;
#pragma unroll
    for (int i = 0; i < 16; i++) {
        int lin = tid + i * 256;
        int qr  = lin >> 6;
        int d   = lin & 63;
        float val = (Obuf[qr * OSTR + d] + Obuf[64 * OSTR + qr * OSTR + d] + vc[d]) * rs[qr];
        g_ctx[((size_t)(b * S_ + q0 + qr)) * D_ + h * 64 + d] = val;
    }
}

// ---------------------------------------------------------------------------
// Normalize attn in place: attn[hb][q][k] *= g_rinv[hb*S+q]
// ---------------------------------------------------------------------------
__global__ __launch_bounds__(256) void attn_norm(float* __restrict__ attn) {
    size_t i = (size_t)blockIdx.x * 256 + threadIdx.x;  // float4 index
    float inv = g_rinv[i >> 9];                          // 512 float4 per row
    float4* p = (float4*)attn;
    float4 v = p[i];
    v.x *= inv; v.y *= inv; v.z *= inv; v.w *= inv;
    p[i] = v;
}

// ---------------------------------------------------------------------------
// LayerNorm over rows of g_dense -> out
// ---------------------------------------------------------------------------
__global__ __launch_bounds__(256) void ln_kernel(const float* __restrict__ lg,
                                                 const float* __restrict__ lb,
                                                 float* __restrict__ out) {
    const int row = blockIdx.x;
    const int tid = threadIdx.x;
    const float* x = g_dense + (size_t)row * 1024;
    float4 xv = *(const float4*)(x + tid * 4);
    float s  = xv.x + xv.y + xv.z + xv.w;
    float ss = fmaf(xv.x, xv.x, fmaf(xv.y, xv.y, fmaf(xv.z, xv.z, xv.w * xv.w)));
#pragma unroll
    for (int off = 16; off > 0; off >>= 1) {
        s  += __shfl_xor_sync(0xffffffffu, s, off);
        ss += __shfl_xor_sync(0xffffffffu, ss, off);
    }
    __shared__ float sm1[8], sm2[8];
    if ((tid & 31) == 0) { sm1[tid >> 5] = s; sm2[tid >> 5] = ss; }
    __syncthreads();
    if (tid < 32) {
        float a  = (tid < 8) ? sm1[tid] : 0.f;
        float b2 = (tid < 8) ? sm2[tid] : 0.f;
#pragma unroll
        for (int off = 4; off > 0; off >>= 1) {
            a  += __shfl_xor_sync(0xffffffffu, a, off);
            b2 += __shfl_xor_sync(0xffffffffu, b2, off);
        }
        if (tid == 0) { sm1[0] = a; sm2[0] = b2; }
    }
    __syncthreads();
    float mean = sm1[0] * (1.0f / 1024.0f);
    float var  = sm2[0] * (1.0f / 1024.0f) - mean * mean;
    float rstd = rsqrtf(var + 1e-5f);
    float4 gv = *(const float4*)(lg + tid * 4);
    float4 bv = *(const float4*)(lb + tid * 4);
    float4 ov;
    ov.x = (xv.x - mean) * rstd * gv.x + bv.x;
    ov.y = (xv.y - mean) * rstd * gv.y + bv.y;
    ov.z = (xv.z - mean) * rstd * gv.z + bv.z;
    ov.w = (xv.w - mean) * rstd * gv.w + bv.w;
    *(float4*)(out + (size_t)row * 1024 + tid * 4) = ov;
}

// ---------------------------------------------------------------------------
// Launch
// ---------------------------------------------------------------------------
extern "C" void kernel_launch(void* const* d_in, const int* in_sizes, int n_in,
                              void* d_out, int out_size) {
    const float* k_in = (const float*)d_in[0];
    const float* q_in = (const float*)d_in[1];
    const float* wk   = (const float*)d_in[2];
    const float* bk   = (const float*)d_in[3];
    const float* wq   = (const float*)d_in[4];
    const float* bq   = (const float*)d_in[5];
    const float* wv   = (const float*)d_in[6];
    const float* bv   = (const float*)d_in[7];
    const float* wd   = (const float*)d_in[8];
    const float* bd   = (const float*)d_in[9];
    const float* lg   = (const float*)d_in[10];
    const float* lb   = (const float*)d_in[11];

    float* out  = (float*)d_out;
    float* attn = out + (size_t)B_ * S_ * D_;  // tuple order: (out, attn)

    const int attn_smem_bytes = ATTN_SMEM_FLOATS * 4;  // 90368 B
    cudaFuncSetAttribute(attn_kernel, cudaFuncAttributeMaxDynamicSharedMemorySize,
                         attn_smem_bytes);

    dim3 pgrid(MTOT / 128, D_ / 128);  // (32, 8)
    qkv_gemm<<<pgrid, 256>>>(q_in, wq, bq, 0);   // g_qx
    qkv_gemm<<<pgrid, 256>>>(k_in, wk, bk, 1);   // g_kx
    qkv_gemm<<<pgrid, 256>>>(k_in, wv, bv, 2);   // g_vx (v = k)

    vcs_kernel<<<HB_, 256>>>();                  // V colsums

    attn_kernel<<<dim3(S_ / 64, HB_), 256, attn_smem_bytes>>>(attn);

    attn_norm<<<131072, 256>>>(attn);

    dense_gemm<<<pgrid, 256>>>(wd, bd);          // dense + relu -> g_dense
    ln_kernel<<<MTOT, 256>>>(lg, lb, out);
}

// round 10
// speedup vs baseline: 1.7831x; 1.0387x over previous
#include <cuda_runtime.h>
#include <cstdint>
#include <cstddef>

// Problem constants
#define B_    2
#define S_    2048
#define D_    1024
#define H_    16
#define DK_   64
#define MTOT  4096        // B_*S_
#define HB_   32          // H_*B_

// ---------------------------------------------------------------------------
// Scratch (static device allocations; no dynamic alloc allowed)
// ---------------------------------------------------------------------------
static __device__ float g_qx[B_ * H_ * S_ * DK_];   // [b][h][s][dk]
static __device__ float g_kx[B_ * H_ * S_ * DK_];
static __device__ float g_vx[B_ * H_ * S_ * DK_];
static __device__ float g_ctx[(size_t)MTOT * D_];   // [b*S+s][h*64+dk]
static __device__ float g_dense[(size_t)MTOT * D_];
static __device__ float g_rinv[HB_ * S_];           // 1/rowsum per attn row
static __device__ float g_vcs[HB_ * DK_];           // colsum of V per (b*H+h, d)

// ---------------------------------------------------------------------------
// Helpers
// ---------------------------------------------------------------------------
__device__ __forceinline__ float tf32_hi(float x) {
    uint32_t r;
    asm("cvt.rna.tf32.f32 %0, %1;" : "=r"(r) : "f"(x));
    return __uint_as_float(r);
}

__device__ __forceinline__ void mma_tf32(float c[4],
                                         uint32_t a0, uint32_t a1, uint32_t a2, uint32_t a3,
                                         uint32_t b0, uint32_t b1) {
    asm volatile(
        "mma.sync.aligned.m16n8k8.row.col.f32.tf32.tf32.f32 "
        "{%0,%1,%2,%3}, {%4,%5,%6,%7}, {%8,%9}, {%0,%1,%2,%3};\n"
        : "+f"(c[0]), "+f"(c[1]), "+f"(c[2]), "+f"(c[3])
        : "r"(a0), "r"(a1), "r"(a2), "r"(a3), "r"(b0), "r"(b1));
}

__device__ __forceinline__ void cp_async16(uint32_t smem_addr, const void* gptr) {
    asm volatile("cp.async.cg.shared.global [%0], [%1], 16;"
                 :: "r"(smem_addr), "l"(gptr));
}

// ---------------------------------------------------------------------------
// QKV projection GEMM v2 (1xTF32, cp.async double-buffered raw staging;
// MMA truncates fp32->tf32 (RZ) — coherent shrink cancels via LN, see notes).
// C[4096x1024] = A @ W^T + bias, scatter to [b][h][s][dk]. mode 0/1/2.
// BM=128 BN=128 BK=16, 256 threads, warps 2(m) x 4(n), warp tile 64x32.
// ---------------------------------------------------------------------------
__global__ __launch_bounds__(256) void qkv_gemm(const float* __restrict__ A,
                                                const float* __restrict__ W,
                                                const float* __restrict__ bias,
                                                int mode) {
    __shared__ float As[2][128 * 20];
    __shared__ float Bs[2][128 * 20];

    const int tid  = threadIdx.x;
    const int lane = tid & 31;
    const int warp = tid >> 5;
    const int wm   = warp & 1;
    const int wn   = warp >> 1;
    const int m0   = blockIdx.x * 128;
    const int n0   = blockIdx.y * 128;

    // staging coords: thread copies chunks tid and tid+256 (of 512 16B chunks)
    const int r0 = tid >> 2;                  // rows 0..63 then 64..127
    const int c0 = (tid & 3) * 4;             // col 0,4,8,12

    float c[4][4][4];
#pragma unroll
    for (int i = 0; i < 4; i++)
#pragma unroll
        for (int j = 0; j < 4; j++)
#pragma unroll
            for (int k = 0; k < 4; k++) c[i][j][k] = 0.f;

    // prologue: stage k0 = 0 into buffer 0
    {
        uint32_t as = (uint32_t)__cvta_generic_to_shared(&As[0][0]);
        uint32_t bs = (uint32_t)__cvta_generic_to_shared(&Bs[0][0]);
#pragma unroll
        for (int i = 0; i < 2; i++) {
            int r = r0 + i * 64;
            cp_async16(as + (r * 20 + c0) * 4, A + (size_t)(m0 + r) * 1024 + c0);
            cp_async16(bs + (r * 20 + c0) * 4, W + (size_t)(n0 + r) * 1024 + c0);
        }
        asm volatile("cp.async.commit_group;");
    }

    for (int kt = 0; kt < 64; kt++) {
        asm volatile("cp.async.wait_group 0;");
        __syncthreads();

        if (kt + 1 < 64) {
            int buf = (kt + 1) & 1;
            int k0  = (kt + 1) * 16;
            uint32_t as = (uint32_t)__cvta_generic_to_shared(&As[buf][0]);
            uint32_t bs = (uint32_t)__cvta_generic_to_shared(&Bs[buf][0]);
#pragma unroll
            for (int i = 0; i < 2; i++) {
                int r = r0 + i * 64;
                cp_async16(as + (r * 20 + c0) * 4, A + (size_t)(m0 + r) * 1024 + k0 + c0);
                cp_async16(bs + (r * 20 + c0) * 4, W + (size_t)(n0 + r) * 1024 + k0 + c0);
            }
            asm volatile("cp.async.commit_group;");
        }

        const float* Ab = As[kt & 1];
        const float* Bb = Bs[kt & 1];
#pragma unroll
        for (int kg = 0; kg < 16; kg += 8) {
            uint32_t bh[4][2];
#pragma unroll
            for (int nt = 0; nt < 4; nt++) {
                int boff = (wn * 32 + nt * 8 + (lane >> 2)) * 20 + kg + (lane & 3);
                bh[nt][0] = __float_as_uint(Bb[boff]);
                bh[nt][1] = __float_as_uint(Bb[boff + 4]);
            }
#pragma unroll
            for (int mt = 0; mt < 4; mt++) {
                int aoff = (wm * 64 + mt * 16 + (lane >> 2)) * 20 + kg + (lane & 3);
                uint32_t a0 = __float_as_uint(Ab[aoff]);
                uint32_t a1 = __float_as_uint(Ab[aoff + 8 * 20]);
                uint32_t a2 = __float_as_uint(Ab[aoff + 4]);
                uint32_t a3 = __float_as_uint(Ab[aoff + 8 * 20 + 4]);
#pragma unroll
                for (int nt = 0; nt < 4; nt++)
                    mma_tf32(c[mt][nt], a0, a1, a2, a3, bh[nt][0], bh[nt][1]);
            }
        }
    }

    __syncthreads();
#pragma unroll
    for (int mt = 0; mt < 4; mt++) {
#pragma unroll
        for (int nt = 0; nt < 4; nt++) {
#pragma unroll
            for (int j = 0; j < 4; j++) {
                int row = m0 + wm * 64 + mt * 16 + (lane >> 2) + ((j >> 1) << 3);
                int col = n0 + wn * 32 + nt * 8 + 2 * (lane & 3) + (j & 1);
                float v = c[mt][nt][j] + bias[col];
                int b  = row >> 11;
                int s  = row & 2047;
                int h  = col >> 6;
                int dk = col & 63;
                float* dst = (mode == 0) ? g_qx : (mode == 1) ? g_kx : g_vx;
                dst[(((size_t)(b * H_ + h)) * S_ + s) * DK_ + dk] = v;
            }
        }
    }
}

// ---------------------------------------------------------------------------
// Dense GEMM v2 (3xTF32 RN via register hi/lo split; cp.async raw staging):
// g_dense = relu(g_ctx @ dense_w^T + dense_b)
// ---------------------------------------------------------------------------
__global__ __launch_bounds__(256) void dense_gemm(const float* __restrict__ W,
                                                  const float* __restrict__ bias) {
    __shared__ float As[2][128 * 20];
    __shared__ float Bs[2][128 * 20];

    const float* Ap = g_ctx;

    const int tid  = threadIdx.x;
    const int lane = tid & 31;
    const int warp = tid >> 5;
    const int wm   = warp & 1;
    const int wn   = warp >> 1;
    const int m0   = blockIdx.x * 128;
    const int n0   = blockIdx.y * 128;

    const int r0 = tid >> 2;
    const int c0 = (tid & 3) * 4;

    float c[4][4][4];
#pragma unroll
    for (int i = 0; i < 4; i++)
#pragma unroll
        for (int j = 0; j < 4; j++)
#pragma unroll
            for (int k = 0; k < 4; k++) c[i][j][k] = 0.f;

    {
        uint32_t as = (uint32_t)__cvta_generic_to_shared(&As[0][0]);
        uint32_t bs = (uint32_t)__cvta_generic_to_shared(&Bs[0][0]);
#pragma unroll
        for (int i = 0; i < 2; i++) {
            int r = r0 + i * 64;
            cp_async16(as + (r * 20 + c0) * 4, Ap + (size_t)(m0 + r) * 1024 + c0);
            cp_async16(bs + (r * 20 + c0) * 4, W + (size_t)(n0 + r) * 1024 + c0);
        }
        asm volatile("cp.async.commit_group;");
    }

    for (int kt = 0; kt < 64; kt++) {
        asm volatile("cp.async.wait_group 0;");
        __syncthreads();

        if (kt + 1 < 64) {
            int buf = (kt + 1) & 1;
            int k0  = (kt + 1) * 16;
            uint32_t as = (uint32_t)__cvta_generic_to_shared(&As[buf][0]);
            uint32_t bs = (uint32_t)__cvta_generic_to_shared(&Bs[buf][0]);
#pragma unroll
            for (int i = 0; i < 2; i++) {
                int r = r0 + i * 64;
                cp_async16(as + (r * 20 + c0) * 4, Ap + (size_t)(m0 + r) * 1024 + k0 + c0);
                cp_async16(bs + (r * 20 + c0) * 4, W + (size_t)(n0 + r) * 1024 + k0 + c0);
            }
            asm volatile("cp.async.commit_group;");
        }

        const float* Ab = As[kt & 1];
        const float* Bb = Bs[kt & 1];
#pragma unroll
        for (int kg = 0; kg < 16; kg += 8) {
            uint32_t bh[4][2], bl[4][2];
#pragma unroll
            for (int nt = 0; nt < 4; nt++) {
                int boff = (wn * 32 + nt * 8 + (lane >> 2)) * 20 + kg + (lane & 3);
                float rb0 = Bb[boff];
                float rb1 = Bb[boff + 4];
                float hb0 = tf32_hi(rb0);
                float hb1 = tf32_hi(rb1);
                bh[nt][0] = __float_as_uint(hb0);
                bh[nt][1] = __float_as_uint(hb1);
                bl[nt][0] = __float_as_uint(rb0 - hb0);
                bl[nt][1] = __float_as_uint(rb1 - hb1);
            }
#pragma unroll
            for (int mt = 0; mt < 4; mt++) {
                int aoff = (wm * 64 + mt * 16 + (lane >> 2)) * 20 + kg + (lane & 3);
                float ra0 = Ab[aoff];
                float ra1 = Ab[aoff + 8 * 20];
                float ra2 = Ab[aoff + 4];
                float ra3 = Ab[aoff + 8 * 20 + 4];
                float ha0 = tf32_hi(ra0), ha1 = tf32_hi(ra1);
                float ha2 = tf32_hi(ra2), ha3 = tf32_hi(ra3);
                uint32_t ah0 = __float_as_uint(ha0), ah1 = __float_as_uint(ha1);
                uint32_t ah2 = __float_as_uint(ha2), ah3 = __float_as_uint(ha3);
                uint32_t al0 = __float_as_uint(ra0 - ha0), al1 = __float_as_uint(ra1 - ha1);
                uint32_t al2 = __float_as_uint(ra2 - ha2), al3 = __float_as_uint(ra3 - ha3);
#pragma unroll
                for (int nt = 0; nt < 4; nt++) {
                    mma_tf32(c[mt][nt], ah0, ah1, ah2, ah3, bh[nt][0], bh[nt][1]);
                    mma_tf32(c[mt][nt], ah0, ah1, ah2, ah3, bl[nt][0], bl[nt][1]);
                    mma_tf32(c[mt][nt], al0, al1, al2, al3, bh[nt][0], bh[nt][1]);
                }
            }
        }
    }

    __syncthreads();
#pragma unroll
    for (int mt = 0; mt < 4; mt++) {
#pragma unroll
        for (int nt = 0; nt < 4; nt++) {
#pragma unroll
            for (int j = 0; j < 4; j++) {
                int row = m0 + wm * 64 + mt * 16 + (lane >> 2) + ((j >> 1) << 3);
                int col = n0 + wn * 32 + nt * 8 + 2 * (lane & 3) + (j & 1);
                float v = c[mt][nt][j] + bias[col];
                g_dense[(size_t)row * 1024 + col] = v > 0.f ? v : 0.f;
            }
        }
    }
}

// ---------------------------------------------------------------------------
// V column-sum per (b*H+h, d):  g_vcs[bh][d] = sum_s g_vx[bh][s][d]
// ---------------------------------------------------------------------------
__global__ __launch_bounds__(256) void vcs_kernel() {
    const int bh = blockIdx.x;
    const float* vb = g_vx + (size_t)bh * S_ * DK_;
    const int d = threadIdx.x & 63;
    const int c = threadIdx.x >> 6;   // 0..3
    float s = 0.f;
    for (int r = c * 512; r < (c + 1) * 512; r++) s += vb[(size_t)r * 64 + d];
    __shared__ float sm[256];
    sm[threadIdx.x] = s;
    __syncthreads();
    if (threadIdx.x < 64)
        g_vcs[bh * 64 + threadIdx.x] =
            sm[threadIdx.x] + sm[threadIdx.x + 64] + sm[threadIdx.x + 128] + sm[threadIdx.x + 192];
}

// ---------------------------------------------------------------------------
// Fused attention kernel (v3: cp.async double-buffered K/V pipeline).
// grid = (S/64, H*B), block = 256 (8 warps: wm 0..3 = q-rows, wn 0..1 = k-half)
// ---------------------------------------------------------------------------
#define KSTR 68
#define VSTR 72
#define KVBUF (64 * KSTR + 64 * VSTR)   // 8960 floats per buffer
#define PSTR 36
#define OSTR 66
#define ATTN_SMEM_FLOATS (2 * KVBUF + 8 * 16 * PSTR + 64)   // 22592 floats = 90368 B

__global__ __launch_bounds__(256, 2) void attn_kernel(float* __restrict__ attn_out) {
    extern __shared__ float smf[];
    float* Pb   = smf + 2 * KVBUF;           // 8 warps x 16 x 36 (dp buffer)
    float* rs   = Pb + 8 * 16 * PSTR;        // rowsum[64]
    float* Obuf = smf;                       // epilogue alias: 2 x 64 x 66

    const int tid  = threadIdx.x;
    const int lane = tid & 31;
    const int warp = tid >> 5;
    const int wm   = warp & 3;               // q-row group
    const int wn   = warp >> 2;              // k half
    const int g    = lane >> 2;
    const int j    = lane & 3;
    const int hb   = blockIdx.y;             // h*B + b
    const int h    = hb >> 1;
    const int b    = hb & 1;
    const int q0   = blockIdx.x * 64;

    const float* qbase = g_qx + ((size_t)(b * H_ + h)) * S_ * DK_;
    const float* kbase = g_kx + ((size_t)(b * H_ + h)) * S_ * DK_;
    const float* vbase = g_vx + ((size_t)(b * H_ + h)) * S_ * DK_;
    const float invT = 0.03125f;             // 1/sqrt(1024)

    if (tid < 64) rs[tid] = 0.f;

    const int sr  = tid >> 4;                // base row 0..15 (+16 per i)
    const int sc4 = (tid & 15) * 4;          // col 0..60

    // prologue: issue tile 0 loads
    {
        float* Kb = smf;
        float* Vb = smf + 64 * KSTR;
        uint32_t ksm = (uint32_t)__cvta_generic_to_shared(Kb);
        uint32_t vsm = (uint32_t)__cvta_generic_to_shared(Vb);
#pragma unroll
        for (int i = 0; i < 4; i++) {
            int r = sr + i * 16;
            cp_async16(ksm + (r * KSTR + sc4) * 4, kbase + (size_t)r * 64 + sc4);
            cp_async16(vsm + (r * VSTR + sc4) * 4, vbase + (size_t)r * 64 + sc4);
        }
        asm volatile("cp.async.commit_group;");
    }

    // Q fragments in registers (RN tf32, pre-scaled)
    uint32_t qa[8][4];
    {
        const float* qr0 = qbase + (size_t)(q0 + wm * 16 + g) * 64;
        const float* qr1 = qr0 + 8 * 64;
#pragma unroll
        for (int kg = 0; kg < 8; kg++) {
            qa[kg][0] = __float_as_uint(tf32_hi(qr0[kg * 8 + j] * invT));
            qa[kg][1] = __float_as_uint(tf32_hi(qr1[kg * 8 + j] * invT));
            qa[kg][2] = __float_as_uint(tf32_hi(qr0[kg * 8 + j + 4] * invT));
            qa[kg][3] = __float_as_uint(tf32_hi(qr1[kg * 8 + j + 4] * invT));
        }
    }

    float o[8][4];
#pragma unroll
    for (int i = 0; i < 8; i++)
#pragma unroll
        for (int k = 0; k < 4; k++) o[i][k] = 0.f;
    float rs0 = 0.f, rs1 = 0.f;
    float* Pw = Pb + warp * 16 * PSTR;

    for (int kt = 0; kt < 32; kt++) {
        float* Kb = smf + (kt & 1) * KVBUF;
        float* Vb = Kb + 64 * KSTR;

        asm volatile("cp.async.wait_group 0;");
        __syncthreads();

        if (kt + 1 < 32) {
            float* Kn = smf + ((kt + 1) & 1) * KVBUF;
            float* Vn = Kn + 64 * KSTR;
            uint32_t ksm = (uint32_t)__cvta_generic_to_shared(Kn);
            uint32_t vsm = (uint32_t)__cvta_generic_to_shared(Vn);
            const float* kb = kbase + (size_t)(kt + 1) * 64 * 64;
            const float* vb = vbase + (size_t)(kt + 1) * 64 * 64;
#pragma unroll
            for (int i = 0; i < 4; i++) {
                int r = sr + i * 16;
                cp_async16(ksm + (r * KSTR + sc4) * 4, kb + (size_t)r * 64 + sc4);
                cp_async16(vsm + (r * VSTR + sc4) * 4, vb + (size_t)r * 64 + sc4);
            }
            asm volatile("cp.async.commit_group;");
        }

        // scores: 16 q-rows x 32 kv (this warp's half); K raw (tf32-truncated)
        float s[4][4];
#pragma unroll
        for (int i = 0; i < 4; i++)
#pragma unroll
            for (int k = 0; k < 4; k++) s[i][k] = 0.f;
#pragma unroll
        for (int kg = 0; kg < 8; kg++) {
#pragma unroll
            for (int nt = 0; nt < 4; nt++) {
                int boff = (wn * 32 + nt * 8 + g) * KSTR + kg * 8 + j;
                mma_tf32(s[nt], qa[kg][0], qa[kg][1], qa[kg][2], qa[kg][3],
                         __float_as_uint(Kb[boff]), __float_as_uint(Kb[boff + 4]));
            }
        }

        // exp -> gmem attn (unnormalized), rowsum regs, dp -> warp smem buffer
        const int k0 = kt * 64;
        float* ab = attn_out + ((size_t)hb * S_ + q0 + wm * 16 + g) * S_ + k0 + wn * 32;
#pragma unroll
        for (int nt = 0; nt < 4; nt++) {
            float p0 = __expf(s[nt][0]);
            float p1 = __expf(s[nt][1]);
            float p2 = __expf(s[nt][2]);
            float p3 = __expf(s[nt][3]);
            rs0 += p0 + p1;
            rs1 += p2 + p3;
            *(float2*)(ab + nt * 8 + 2 * j) = make_float2(p0, p1);
            *(float2*)(ab + (size_t)8 * S_ + nt * 8 + 2 * j) = make_float2(p2, p3);
            *(float2*)(Pw + g * PSTR + nt * 8 + 2 * j)       = make_float2(p0 - 1.f, p1 - 1.f);
            *(float2*)(Pw + (g + 8) * PSTR + nt * 8 + 2 * j) = make_float2(p2 - 1.f, p3 - 1.f);
        }
        __syncwarp();

        // O_half += dp @ V over this warp's 32-k half
#pragma unroll
        for (int kp = 0; kp < 4; kp++) {
            uint32_t a0 = __float_as_uint(Pw[g * PSTR + kp * 8 + j]);
            uint32_t a1 = __float_as_uint(Pw[(g + 8) * PSTR + kp * 8 + j]);
            uint32_t a2 = __float_as_uint(Pw[g * PSTR + kp * 8 + j + 4]);
            uint32_t a3 = __float_as_uint(Pw[(g + 8) * PSTR + kp * 8 + j + 4]);
#pragma unroll
            for (int nv = 0; nv < 8; nv++) {
                int boff = (wn * 32 + kp * 8 + j) * VSTR + nv * 8 + g;
                mma_tf32(o[nv], a0, a1, a2, a3,
                         __float_as_uint(Vb[boff]), __float_as_uint(Vb[boff + 4 * VSTR]));
            }
        }
    }

    // --- epilogue ---
    __syncthreads();   // all PV reads of the KV buffers complete before aliasing
    float* Ob = Obuf + wn * 64 * OSTR + (wm * 16) * OSTR;
#pragma unroll
    for (int nv = 0; nv < 8; nv++) {
        *(float2*)(Ob + g * OSTR + nv * 8 + 2 * j)       = make_float2(o[nv][0], o[nv][1]);
        *(float2*)(Ob + (g + 8) * OSTR + nv * 8 + 2 * j) = make_float2(o[nv][2], o[nv][3]);
    }
    rs0 += __shfl_xor_sync(0xffffffffu, rs0, 1);
    rs0 += __shfl_xor_sync(0xffffffffu, rs0, 2);
    rs1 += __shfl_xor_sync(0xffffffffu, rs1, 1);
    rs1 += __shfl_xor_sync(0xffffffffu, rs1, 2);
    if (j == 0) {
        atomicAdd(&rs[wm * 16 + g], rs0);
        atomicAdd(&rs[wm * 16 + 8 + g], rs1);
    }
    __syncthreads();
    if (tid < 64) {
        float inv = 1.0f / rs[tid];
        g_rinv[(size_t)hb * S_ + q0 + tid] = inv;
        rs[tid] = inv;
    }
    __syncthreads();

    const float* vc = g_vcs + (b * H_ + h) * 64;
#pragma unroll
    for (int i = 0; i < 16; i++) {
        int lin = tid + i * 256;
        int qr  = lin >> 6;
        int d   = lin & 63;
        float val = (Obuf[qr * OSTR + d] + Obuf[64 * OSTR + qr * OSTR + d] + vc[d]) * rs[qr];
        g_ctx[((size_t)(b * S_ + q0 + qr)) * D_ + h * 64 + d] = val;
    }
}

// ---------------------------------------------------------------------------
// Normalize attn in place: attn[hb][q][k] *= g_rinv[hb*S+q]
// ---------------------------------------------------------------------------
__global__ __launch_bounds__(256) void attn_norm(float* __restrict__ attn) {
    size_t i = (size_t)blockIdx.x * 256 + threadIdx.x;  // float4 index
    float inv = g_rinv[i >> 9];                          // 512 float4 per row
    float4* p = (float4*)attn;
    float4 v = p[i];
    v.x *= inv; v.y *= inv; v.z *= inv; v.w *= inv;
    p[i] = v;
}

// ---------------------------------------------------------------------------
// LayerNorm over rows of g_dense -> out
// ---------------------------------------------------------------------------
__global__ __launch_bounds__(256) void ln_kernel(const float* __restrict__ lg,
                                                 const float* __restrict__ lb,
                                                 float* __restrict__ out) {
    const int row = blockIdx.x;
    const int tid = threadIdx.x;
    const float* x = g_dense + (size_t)row * 1024;
    float4 xv = *(const float4*)(x + tid * 4);
    float s  = xv.x + xv.y + xv.z + xv.w;
    float ss = fmaf(xv.x, xv.x, fmaf(xv.y, xv.y, fmaf(xv.z, xv.z, xv.w * xv.w)));
#pragma unroll
    for (int off = 16; off > 0; off >>= 1) {
        s  += __shfl_xor_sync(0xffffffffu, s, off);
        ss += __shfl_xor_sync(0xffffffffu, ss, off);
    }
    __shared__ float sm1[8], sm2[8];
    if ((tid & 31) == 0) { sm1[tid >> 5] = s; sm2[tid >> 5] = ss; }
    __syncthreads();
    if (tid < 32) {
        float a  = (tid < 8) ? sm1[tid] : 0.f;
        float b2 = (tid < 8) ? sm2[tid] : 0.f;
#pragma unroll
        for (int off = 4; off > 0; off >>= 1) {
            a  += __shfl_xor_sync(0xffffffffu, a, off);
            b2 += __shfl_xor_sync(0xffffffffu, b2, off);
        }
        if (tid == 0) { sm1[0] = a; sm2[0] = b2; }
    }
    __syncthreads();
    float mean = sm1[0] * (1.0f / 1024.0f);
    float var  = sm2[0] * (1.0f / 1024.0f) - mean * mean;
    float rstd = rsqrtf(var + 1e-5f);
    float4 gv = *(const float4*)(lg + tid * 4);
    float4 bv = *(const float4*)(lb + tid * 4);
    float4 ov;
    ov.x = (xv.x - mean) * rstd * gv.x + bv.x;
    ov.y = (xv.y - mean) * rstd * gv.y + bv.y;
    ov.z = (xv.z - mean) * rstd * gv.z + bv.z;
    ov.w = (xv.w - mean) * rstd * gv.w + bv.w;
    *(float4*)(out + (size_t)row * 1024 + tid * 4) = ov;
}

// ---------------------------------------------------------------------------
// Launch
// ---------------------------------------------------------------------------
extern "C" void kernel_launch(void* const* d_in, const int* in_sizes, int n_in,
                              void* d_out, int out_size) {
    const float* k_in = (const float*)d_in[0];
    const float* q_in = (const float*)d_in[1];
    const float* wk   = (const float*)d_in[2];
    const float* bk   = (const float*)d_in[3];
    const float* wq   = (const float*)d_in[4];
    const float* bq   = (const float*)d_in[5];
    const float* wv   = (const float*)d_in[6];
    const float* bv   = (const float*)d_in[7];
    const float* wd   = (const float*)d_in[8];
    const float* bd   = (const float*)d_in[9];
    const float* lg   = (const float*)d_in[10];
    const float* lb   = (const float*)d_in[11];

    float* out  = (float*)d_out;
    float* attn = out + (size_t)B_ * S_ * D_;  // tuple order: (out, attn)

    const int attn_smem_bytes = ATTN_SMEM_FLOATS * 4;  // 90368 B
    cudaFuncSetAttribute(attn_kernel, cudaFuncAttributeMaxDynamicSharedMemorySize,
                         attn_smem_bytes);

    dim3 pgrid(MTOT / 128, D_ / 128);  // (32, 8)
    qkv_gemm<<<pgrid, 256>>>(q_in, wq, bq, 0);   // g_qx
    qkv_gemm<<<pgrid, 256>>>(k_in, wk, bk, 1);   // g_kx
    qkv_gemm<<<pgrid, 256>>>(k_in, wv, bv, 2);   // g_vx (v = k)

    vcs_kernel<<<HB_, 256>>>();                  // V colsums

    attn_kernel<<<dim3(S_ / 64, HB_), 256, attn_smem_bytes>>>(attn);

    attn_norm<<<131072, 256>>>(attn);

    dense_gemm<<<pgrid, 256>>>(wd, bd);          // dense + relu -> g_dense
    ln_kernel<<<MTOT, 256>>>(lg, lb, out);
}

// round 12
// speedup vs baseline: 1.8286x; 1.0256x over previous
#include <cuda_runtime.h>
#include <cstdint>
#include <cstddef>

// Problem constants
#define B_    2
#define S_    2048
#define D_    1024
#define H_    16
#define DK_   64
#define MTOT  4096        // B_*S_
#define HB_   32          // H_*B_

// ---------------------------------------------------------------------------
// Scratch (static device allocations; no dynamic alloc allowed)
// g_qx / g_kx store the dk axis PERMUTED: dk' = (dk&56)|((dk&3)<<1)|((dk>>2)&1)
// (scores are invariant; enables paired LDS.64 B-fragment loads in attn).
// g_vx is natural layout (PV + colsum need it).
// ---------------------------------------------------------------------------
static __device__ float g_qx[B_ * H_ * S_ * DK_];   // [b][h][s][dk']
static __device__ float g_kx[B_ * H_ * S_ * DK_];   // [b][h][s][dk']
static __device__ float g_vx[B_ * H_ * S_ * DK_];   // [b][h][s][dk]
static __device__ float g_ctx[(size_t)MTOT * D_];   // [b*S+s][h*64+dk]
static __device__ float g_dense[(size_t)MTOT * D_];
static __device__ float g_rinv[HB_ * S_];           // 1/rowsum per attn row
static __device__ float g_vcs[HB_ * DK_];           // colsum of V per (b*H+h, d)

// ---------------------------------------------------------------------------
// Helpers
// ---------------------------------------------------------------------------
__device__ __forceinline__ float tf32_hi(float x) {
    uint32_t r;
    asm("cvt.rna.tf32.f32 %0, %1;" : "=r"(r) : "f"(x));
    return __uint_as_float(r);
}

__device__ __forceinline__ void mma_tf32(float c[4],
                                         uint32_t a0, uint32_t a1, uint32_t a2, uint32_t a3,
                                         uint32_t b0, uint32_t b1) {
    asm volatile(
        "mma.sync.aligned.m16n8k8.row.col.f32.tf32.tf32.f32 "
        "{%0,%1,%2,%3}, {%4,%5,%6,%7}, {%8,%9}, {%0,%1,%2,%3};\n"
        : "+f"(c[0]), "+f"(c[1]), "+f"(c[2]), "+f"(c[3])
        : "r"(a0), "r"(a1), "r"(a2), "r"(a3), "r"(b0), "r"(b1));
}

__device__ __forceinline__ void cp_async16(uint32_t smem_addr, const void* gptr) {
    asm volatile("cp.async.cg.shared.global [%0], [%1], 16;"
                 :: "r"(smem_addr), "l"(gptr));
}

// ---------------------------------------------------------------------------
// QKV projection GEMM (1xTF32, cp.async double-buffered raw staging).
// mode 0 -> g_qx (permuted dk, also zeroes g_vcs), mode 1 -> g_kx (permuted),
// mode 2 -> g_vx (natural dk, accumulates g_vcs colsums via atomics).
// ---------------------------------------------------------------------------
__global__ __launch_bounds__(256) void qkv_gemm(const float* __restrict__ A,
                                                const float* __restrict__ W,
                                                const float* __restrict__ bias,
                                                int mode) {
    __shared__ float As[2][128 * 20];
    __shared__ float Bs[2][128 * 20];

    const int tid  = threadIdx.x;
    const int lane = tid & 31;
    const int warp = tid >> 5;
    const int wm   = warp & 1;
    const int wn   = warp >> 1;
    const int m0   = blockIdx.x * 128;
    const int n0   = blockIdx.y * 128;

    // mode 0 runs in an earlier launch than mode 2: zero the colsum buffer here.
    if (mode == 0 && blockIdx.x == 0 && blockIdx.y == 0) {
#pragma unroll
        for (int i = 0; i < 8; i++) g_vcs[tid + i * 256] = 0.f;
    }

    const int r0 = tid >> 2;                  // rows 0..63 then 64..127
    const int c0 = (tid & 3) * 4;             // col 0,4,8,12

    float c[4][4][4];
#pragma unroll
    for (int i = 0; i < 4; i++)
#pragma unroll
        for (int j = 0; j < 4; j++)
#pragma unroll
            for (int k = 0; k < 4; k++) c[i][j][k] = 0.f;

    {
        uint32_t as = (uint32_t)__cvta_generic_to_shared(&As[0][0]);
        uint32_t bs = (uint32_t)__cvta_generic_to_shared(&Bs[0][0]);
#pragma unroll
        for (int i = 0; i < 2; i++) {
            int r = r0 + i * 64;
            cp_async16(as + (r * 20 + c0) * 4, A + (size_t)(m0 + r) * 1024 + c0);
            cp_async16(bs + (r * 20 + c0) * 4, W + (size_t)(n0 + r) * 1024 + c0);
        }
        asm volatile("cp.async.commit_group;");
    }

    for (int kt = 0; kt < 64; kt++) {
        asm volatile("cp.async.wait_group 0;");
        __syncthreads();

        if (kt + 1 < 64) {
            int buf = (kt + 1) & 1;
            int k0  = (kt + 1) * 16;
            uint32_t as = (uint32_t)__cvta_generic_to_shared(&As[buf][0]);
            uint32_t bs = (uint32_t)__cvta_generic_to_shared(&Bs[buf][0]);
#pragma unroll
            for (int i = 0; i < 2; i++) {
                int r = r0 + i * 64;
                cp_async16(as + (r * 20 + c0) * 4, A + (size_t)(m0 + r) * 1024 + k0 + c0);
                cp_async16(bs + (r * 20 + c0) * 4, W + (size_t)(n0 + r) * 1024 + k0 + c0);
            }
            asm volatile("cp.async.commit_group;");
        }

        const float* Ab = As[kt & 1];
        const float* Bb = Bs[kt & 1];
#pragma unroll
        for (int kg = 0; kg < 16; kg += 8) {
            uint32_t bh[4][2];
#pragma unroll
            for (int nt = 0; nt < 4; nt++) {
                int boff = (wn * 32 + nt * 8 + (lane >> 2)) * 20 + kg + (lane & 3);
                bh[nt][0] = __float_as_uint(Bb[boff]);
                bh[nt][1] = __float_as_uint(Bb[boff + 4]);
            }
#pragma unroll
            for (int mt = 0; mt < 4; mt++) {
                int aoff = (wm * 64 + mt * 16 + (lane >> 2)) * 20 + kg + (lane & 3);
                uint32_t a0 = __float_as_uint(Ab[aoff]);
                uint32_t a1 = __float_as_uint(Ab[aoff + 8 * 20]);
                uint32_t a2 = __float_as_uint(Ab[aoff + 4]);
                uint32_t a3 = __float_as_uint(Ab[aoff + 8 * 20 + 4]);
#pragma unroll
                for (int nt = 0; nt < 4; nt++)
                    mma_tf32(c[mt][nt], a0, a1, a2, a3, bh[nt][0], bh[nt][1]);
            }
        }
    }

    __syncthreads();

    float csum[4][2];                         // [nt][col parity], mode 2 only
#pragma unroll
    for (int nt = 0; nt < 4; nt++) { csum[nt][0] = 0.f; csum[nt][1] = 0.f; }

#pragma unroll
    for (int mt = 0; mt < 4; mt++) {
#pragma unroll
        for (int nt = 0; nt < 4; nt++) {
#pragma unroll
            for (int j = 0; j < 4; j++) {
                int row = m0 + wm * 64 + mt * 16 + (lane >> 2) + ((j >> 1) << 3);
                int col = n0 + wn * 32 + nt * 8 + 2 * (lane & 3) + (j & 1);
                float v = c[mt][nt][j] + bias[col];
                int b  = row >> 11;
                int s  = row & 2047;
                int h  = col >> 6;
                int dk = col & 63;
                if (mode == 2) {
                    csum[nt][j & 1] += v;
                    g_vx[(((size_t)(b * H_ + h)) * S_ + s) * DK_ + dk] = v;
                } else {
                    int dkp = (dk & 56) | ((dk & 3) << 1) | ((dk >> 2) & 1);
                    float* dst = (mode == 0) ? g_qx : g_kx;
                    dst[(((size_t)(b * H_ + h)) * S_ + s) * DK_ + dkp] = v;
                }
            }
        }
    }

    if (mode == 2) {
        // reduce colsums across the 8 lanes sharing a column (lane stride 4)
#pragma unroll
        for (int nt = 0; nt < 4; nt++) {
#pragma unroll
            for (int p = 0; p < 2; p++) {
                float v = csum[nt][p];
                v += __shfl_down_sync(0xffffffffu, v, 16);
                v += __shfl_down_sync(0xffffffffu, v, 8);
                v += __shfl_down_sync(0xffffffffu, v, 4);
                if (lane < 4) {
                    int col = n0 + wn * 32 + nt * 8 + 2 * lane + p;
                    int b   = m0 >> 11;
                    int bh  = b * H_ + (col >> 6);
                    atomicAdd(&g_vcs[bh * 64 + (col & 63)], v);
                }
            }
        }
    }
}

// ---------------------------------------------------------------------------
// Dense GEMM (3xTF32 RN via register hi/lo split; cp.async raw staging):
// g_dense = relu(g_ctx @ dense_w^T + dense_b)
// ---------------------------------------------------------------------------
__global__ __launch_bounds__(256) void dense_gemm(const float* __restrict__ W,
                                                  const float* __restrict__ bias) {
    __shared__ float As[2][128 * 20];
    __shared__ float Bs[2][128 * 20];

    const float* Ap = g_ctx;

    const int tid  = threadIdx.x;
    const int lane = tid & 31;
    const int warp = tid >> 5;
    const int wm   = warp & 1;
    const int wn   = warp >> 1;
    const int m0   = blockIdx.x * 128;
    const int n0   = blockIdx.y * 128;

    const int r0 = tid >> 2;
    const int c0 = (tid & 3) * 4;

    float c[4][4][4];
#pragma unroll
    for (int i = 0; i < 4; i++)
#pragma unroll
        for (int j = 0; j < 4; j++)
#pragma unroll
            for (int k = 0; k < 4; k++) c[i][j][k] = 0.f;

    {
        uint32_t as = (uint32_t)__cvta_generic_to_shared(&As[0][0]);
        uint32_t bs = (uint32_t)__cvta_generic_to_shared(&Bs[0][0]);
#pragma unroll
        for (int i = 0; i < 2; i++) {
            int r = r0 + i * 64;
            cp_async16(as + (r * 20 + c0) * 4, Ap + (size_t)(m0 + r) * 1024 + c0);
            cp_async16(bs + (r * 20 + c0) * 4, W + (size_t)(n0 + r) * 1024 + c0);
        }
        asm volatile("cp.async.commit_group;");
    }

    for (int kt = 0; kt < 64; kt++) {
        asm volatile("cp.async.wait_group 0;");
        __syncthreads();

        if (kt + 1 < 64) {
            int buf = (kt + 1) & 1;
            int k0  = (kt + 1) * 16;
            uint32_t as = (uint32_t)__cvta_generic_to_shared(&As[buf][0]);
            uint32_t bs = (uint32_t)__cvta_generic_to_shared(&Bs[buf][0]);
#pragma unroll
            for (int i = 0; i < 2; i++) {
                int r = r0 + i * 64;
                cp_async16(as + (r * 20 + c0) * 4, Ap + (size_t)(m0 + r) * 1024 + k0 + c0);
                cp_async16(bs + (r * 20 + c0) * 4, W + (size_t)(n0 + r) * 1024 + k0 + c0);
            }
            asm volatile("cp.async.commit_group;");
        }

        const float* Ab = As[kt & 1];
        const float* Bb = Bs[kt & 1];
#pragma unroll
        for (int kg = 0; kg < 16; kg += 8) {
            uint32_t bh[4][2], bl[4][2];
#pragma unroll
            for (int nt = 0; nt < 4; nt++) {
                int boff = (wn * 32 + nt * 8 + (lane >> 2)) * 20 + kg + (lane & 3);
                float rb0 = Bb[boff];
                float rb1 = Bb[boff + 4];
                float hb0 = tf32_hi(rb0);
                float hb1 = tf32_hi(rb1);
                bh[nt][0] = __float_as_uint(hb0);
                bh[nt][1] = __float_as_uint(hb1);
                bl[nt][0] = __float_as_uint(rb0 - hb0);
                bl[nt][1] = __float_as_uint(rb1 - hb1);
            }
#pragma unroll
            for (int mt = 0; mt < 4; mt++) {
                int aoff = (wm * 64 + mt * 16 + (lane >> 2)) * 20 + kg + (lane & 3);
                float ra0 = Ab[aoff];
                float ra1 = Ab[aoff + 8 * 20];
                float ra2 = Ab[aoff + 4];
                float ra3 = Ab[aoff + 8 * 20 + 4];
                float ha0 = tf32_hi(ra0), ha1 = tf32_hi(ra1);
                float ha2 = tf32_hi(ra2), ha3 = tf32_hi(ra3);
                uint32_t ah0 = __float_as_uint(ha0), ah1 = __float_as_uint(ha1);
                uint32_t ah2 = __float_as_uint(ha2), ah3 = __float_as_uint(ha3);
                uint32_t al0 = __float_as_uint(ra0 - ha0), al1 = __float_as_uint(ra1 - ha1);
                uint32_t al2 = __float_as_uint(ra2 - ha2), al3 = __float_as_uint(ra3 - ha3);
#pragma unroll
                for (int nt = 0; nt < 4; nt++) {
                    mma_tf32(c[mt][nt], ah0, ah1, ah2, ah3, bh[nt][0], bh[nt][1]);
                    mma_tf32(c[mt][nt], ah0, ah1, ah2, ah3, bl[nt][0], bl[nt][1]);
                    mma_tf32(c[mt][nt], al0, al1, al2, al3, bh[nt][0], bh[nt][1]);
                }
            }
        }
    }

    __syncthreads();
#pragma unroll
    for (int mt = 0; mt < 4; mt++) {
#pragma unroll
        for (int nt = 0; nt < 4; nt++) {
#pragma unroll
            for (int j = 0; j < 4; j++) {
                int row = m0 + wm * 64 + mt * 16 + (lane >> 2) + ((j >> 1) << 3);
                int col = n0 + wn * 32 + nt * 8 + 2 * (lane & 3) + (j & 1);
                float v = c[mt][nt][j] + bias[col];
                g_dense[(size_t)row * 1024 + col] = v > 0.f ? v : 0.f;
            }
        }
    }
}

// ---------------------------------------------------------------------------
// Fused attention kernel (v4: cp.async pipeline + paired LDS.64 score frags).
// grid = (S/64, H*B), block = 256 (8 warps: wm 0..3 = q-rows, wn 0..1 = k-half)
// Q/K gmem have permuted dk (pairs (j, j+4) adjacent): score B-frag = 1 float2.
// KSTR = 72 (36 pairs ≡ 4 mod 16) -> conflict-free paired loads.
// ---------------------------------------------------------------------------
#define KSTR 72
#define VSTR 72
#define KVBUF (64 * KSTR + 64 * VSTR)   // 9216 floats per buffer
#define PSTR 36
#define OSTR 66
#define ATTN_SMEM_FLOATS (2 * KVBUF + 8 * 16 * PSTR + 64)   // 23104 floats = 92416 B

__global__ __launch_bounds__(256, 2) void attn_kernel(float* __restrict__ attn_out) {
    extern __shared__ float smf[];
    float* Pb   = smf + 2 * KVBUF;           // 8 warps x 16 x 36 (dp buffer)
    float* rs   = Pb + 8 * 16 * PSTR;        // rowsum[64]
    float* Obuf = smf;                       // epilogue alias: 2 x 64 x 66

    const int tid  = threadIdx.x;
    const int lane = tid & 31;
    const int warp = tid >> 5;
    const int wm   = warp & 3;               // q-row group
    const int wn   = warp >> 2;              // k half
    const int g    = lane >> 2;
    const int j    = lane & 3;
    const int hb   = blockIdx.y;             // h*B + b
    const int h    = hb >> 1;
    const int b    = hb & 1;
    const int q0   = blockIdx.x * 64;

    const float* qbase = g_qx + ((size_t)(b * H_ + h)) * S_ * DK_;
    const float* kbase = g_kx + ((size_t)(b * H_ + h)) * S_ * DK_;
    const float* vbase = g_vx + ((size_t)(b * H_ + h)) * S_ * DK_;
    const float invT = 0.03125f;             // 1/sqrt(1024)

    if (tid < 64) rs[tid] = 0.f;

    const int sr  = tid >> 4;                // base row 0..15 (+16 per i)
    const int sc4 = (tid & 15) * 4;          // col 0..60

    // prologue: issue tile 0 loads
    {
        float* Kb = smf;
        float* Vb = smf + 64 * KSTR;
        uint32_t ksm = (uint32_t)__cvta_generic_to_shared(Kb);
        uint32_t vsm = (uint32_t)__cvta_generic_to_shared(Vb);
#pragma unroll
        for (int i = 0; i < 4; i++) {
            int r = sr + i * 16;
            cp_async16(ksm + (r * KSTR + sc4) * 4, kbase + (size_t)r * 64 + sc4);
            cp_async16(vsm + (r * VSTR + sc4) * 4, vbase + (size_t)r * 64 + sc4);
        }
        asm volatile("cp.async.commit_group;");
    }

    // Q fragments in registers (RN tf32, pre-scaled). Permuted layout: natural
    // cols (kg*8+j, kg*8+j+4) sit at permuted offsets kg*8+2j, +2j+1 -> float2.
    uint32_t qa[8][4];
    {
        const float* qr0 = qbase + (size_t)(q0 + wm * 16 + g) * 64;
        const float* qr1 = qr0 + 8 * 64;
#pragma unroll
        for (int kg = 0; kg < 8; kg++) {
            float2 u0 = *(const float2*)(qr0 + kg * 8 + 2 * j);
            float2 u1 = *(const float2*)(qr1 + kg * 8 + 2 * j);
            qa[kg][0] = __float_as_uint(tf32_hi(u0.x * invT));
            qa[kg][2] = __float_as_uint(tf32_hi(u0.y * invT));
            qa[kg][1] = __float_as_uint(tf32_hi(u1.x * invT));
            qa[kg][3] = __float_as_uint(tf32_hi(u1.y * invT));
        }
    }

    float o[8][4];
#pragma unroll
    for (int i = 0; i < 8; i++)
#pragma unroll
        for (int k = 0; k < 4; k++) o[i][k] = 0.f;
    float rs0 = 0.f, rs1 = 0.f;
    float* Pw = Pb + warp * 16 * PSTR;

    for (int kt = 0; kt < 32; kt++) {
        float* Kb = smf + (kt & 1) * KVBUF;
        float* Vb = Kb + 64 * KSTR;

        asm volatile("cp.async.wait_group 0;");
        __syncthreads();

        if (kt + 1 < 32) {
            float* Kn = smf + ((kt + 1) & 1) * KVBUF;
            float* Vn = Kn + 64 * KSTR;
            uint32_t ksm = (uint32_t)__cvta_generic_to_shared(Kn);
            uint32_t vsm = (uint32_t)__cvta_generic_to_shared(Vn);
            const float* kb = kbase + (size_t)(kt + 1) * 64 * 64;
            const float* vb = vbase + (size_t)(kt + 1) * 64 * 64;
#pragma unroll
            for (int i = 0; i < 4; i++) {
                int r = sr + i * 16;
                cp_async16(ksm + (r * KSTR + sc4) * 4, kb + (size_t)r * 64 + sc4);
                cp_async16(vsm + (r * VSTR + sc4) * 4, vb + (size_t)r * 64 + sc4);
            }
            asm volatile("cp.async.commit_group;");
        }

        // scores: paired B-frag loads (permuted K layout)
        float s[4][4];
#pragma unroll
        for (int i = 0; i < 4; i++)
#pragma unroll
            for (int k = 0; k < 4; k++) s[i][k] = 0.f;
#pragma unroll
        for (int kg = 0; kg < 8; kg++) {
#pragma unroll
            for (int nt = 0; nt < 4; nt++) {
                int boff = (wn * 32 + nt * 8 + g) * KSTR + kg * 8 + 2 * j;
                float2 kb2 = *(const float2*)(Kb + boff);
                mma_tf32(s[nt], qa[kg][0], qa[kg][1], qa[kg][2], qa[kg][3],
                         __float_as_uint(kb2.x), __float_as_uint(kb2.y));
            }
        }

        // exp -> gmem attn (unnormalized), rowsum regs, dp -> warp smem buffer
        const int k0 = kt * 64;
        float* ab = attn_out + ((size_t)hb * S_ + q0 + wm * 16 + g) * S_ + k0 + wn * 32;
#pragma unroll
        for (int nt = 0; nt < 4; nt++) {
            float p0 = __expf(s[nt][0]);
            float p1 = __expf(s[nt][1]);
            float p2 = __expf(s[nt][2]);
            float p3 = __expf(s[nt][3]);
            rs0 += p0 + p1;
            rs1 += p2 + p3;
            *(float2*)(ab + nt * 8 + 2 * j) = make_float2(p0, p1);
            *(float2*)(ab + (size_t)8 * S_ + nt * 8 + 2 * j) = make_float2(p2, p3);
            *(float2*)(Pw + g * PSTR + nt * 8 + 2 * j)       = make_float2(p0 - 1.f, p1 - 1.f);
            *(float2*)(Pw + (g + 8) * PSTR + nt * 8 + 2 * j) = make_float2(p2 - 1.f, p3 - 1.f);
        }
        __syncwarp();

        // O_half += dp @ V over this warp's 32-k half (natural V layout)
#pragma unroll
        for (int kp = 0; kp < 4; kp++) {
            uint32_t a0 = __float_as_uint(Pw[g * PSTR + kp * 8 + j]);
            uint32_t a1 = __float_as_uint(Pw[(g + 8) * PSTR + kp * 8 + j]);
            uint32_t a2 = __float_as_uint(Pw[g * PSTR + kp * 8 + j + 4]);
            uint32_t a3 = __float_as_uint(Pw[(g + 8) * PSTR + kp * 8 + j + 4]);
#pragma unroll
            for (int nv = 0; nv < 8; nv++) {
                int boff = (wn * 32 + kp * 8 + j) * VSTR + nv * 8 + g;
                mma_tf32(o[nv], a0, a1, a2, a3,
                         __float_as_uint(Vb[boff]), __float_as_uint(Vb[boff + 4 * VSTR]));
            }
        }
    }

    // --- epilogue ---
    __syncthreads();   // all PV reads of the KV buffers complete before aliasing
    float* Ob = Obuf + wn * 64 * OSTR + (wm * 16) * OSTR;
#pragma unroll
    for (int nv = 0; nv < 8; nv++) {
        *(float2*)(Ob + g * OSTR + nv * 8 + 2 * j)       = make_float2(o[nv][0], o[nv][1]);
        *(float2*)(Ob + (g + 8) * OSTR + nv * 8 + 2 * j) = make_float2(o[nv][2], o[nv][3]);
    }
    rs0 += __shfl_xor_sync(0xffffffffu, rs0, 1);
    rs0 += __shfl_xor_sync(0xffffffffu, rs0, 2);
    rs1 += __shfl_xor_sync(0xffffffffu, rs1, 1);
    rs1 += __shfl_xor_sync(0xffffffffu, rs1, 2);
    if (j == 0) {
        atomicAdd(&rs[wm * 16 + g], rs0);
        atomicAdd(&rs[wm * 16 + 8 + g], rs1);
    }
    __syncthreads();
    if (tid < 64) {
        float inv = 1.0f / rs[tid];
        g_rinv[(size_t)hb * S_ + q0 + tid] = inv;
        rs[tid] = inv;
    }
    __syncthreads();

    const float* vc = g_vcs + (b * H_ + h) * 64;
#pragma unroll
    for (int i = 0; i < 16; i++) {
        int lin = tid + i * 256;
        int qr  = lin >> 6;
        int d   = lin & 63;
        float val = (Obuf[qr * OSTR + d] + Obuf[64 * OSTR + qr * OSTR + d] + vc[d]) * rs[qr];
        g_ctx[((size_t)(b * S_ + q0 + qr)) * D_ + h * 64 + d] = val;
    }
}

// ---------------------------------------------------------------------------
// Normalize attn in place: attn[hb][q][k] *= g_rinv[hb*S+q]
// ---------------------------------------------------------------------------
__global__ __launch_bounds__(256) void attn_norm(float* __restrict__ attn) {
    size_t i = (size_t)blockIdx.x * 256 + threadIdx.x;  // float4 index
    float inv = g_rinv[i >> 9];                          // 512 float4 per row
    float4* p = (float4*)attn;
    float4 v = p[i];
    v.x *= inv; v.y *= inv; v.z *= inv; v.w *= inv;
    p[i] = v;
}

// ---------------------------------------------------------------------------
// LayerNorm over rows of g_dense -> out
// ---------------------------------------------------------------------------
__global__ __launch_bounds__(256) void ln_kernel(const float* __restrict__ lg,
                                                 const float* __restrict__ lb,
                                                 float* __restrict__ out) {
    const int row = blockIdx.x;
    const int tid = threadIdx.x;
    const float* x = g_dense + (size_t)row * 1024;
    float4 xv = *(const float4*)(x + tid * 4);
    float s  = xv.x + xv.y + xv.z + xv.w;
    float ss = fmaf(xv.x, xv.x, fmaf(xv.y, xv.y, fmaf(xv.z, xv.z, xv.w * xv.w)));
#pragma unroll
    for (int off = 16; off > 0; off >>= 1) {
        s  += __shfl_xor_sync(0xffffffffu, s, off);
        ss += __shfl_xor_sync(0xffffffffu, ss, off);
    }
    __shared__ float sm1[8], sm2[8];
    if ((tid & 31) == 0) { sm1[tid >> 5] = s; sm2[tid >> 5] = ss; }
    __syncthreads();
    if (tid < 32) {
        float a  = (tid < 8) ? sm1[tid] : 0.f;
        float b2 = (tid < 8) ? sm2[tid] : 0.f;
#pragma unroll
        for (int off = 4; off > 0; off >>= 1) {
            a  += __shfl_xor_sync(0xffffffffu, a, off);
            b2 += __shfl_xor_sync(0xffffffffu, b2, off);
        }
        if (tid == 0) { sm1[0] = a; sm2[0] = b2; }
    }
    __syncthreads();
    float mean = sm1[0] * (1.0f / 1024.0f);
    float var  = sm2[0] * (1.0f / 1024.0f) - mean * mean;
    float rstd = rsqrtf(var + 1e-5f);
    float4 gv = *(const float4*)(lg + tid * 4);
    float4 bv = *(const float4*)(lb + tid * 4);
    float4 ov;
    ov.x = (xv.x - mean) * rstd * gv.x + bv.x;
    ov.y = (xv.y - mean) * rstd * gv.y + bv.y;
    ov.z = (xv.z - mean) * rstd * gv.z + bv.z;
    ov.w = (xv.w - mean) * rstd * gv.w + bv.w;
    *(float4*)(out + (size_t)row * 1024 + tid * 4) = ov;
}

// ---------------------------------------------------------------------------
// Launch (7 launches; attn is #4 so the harness ncu capture samples it)
// ---------------------------------------------------------------------------
extern "C" void kernel_launch(void* const* d_in, const int* in_sizes, int n_in,
                              void* d_out, int out_size) {
    const float* k_in = (const float*)d_in[0];
    const float* q_in = (const float*)d_in[1];
    const float* wk   = (const float*)d_in[2];
    const float* bk   = (const float*)d_in[3];
    const float* wq   = (const float*)d_in[4];
    const float* bq   = (const float*)d_in[5];
    const float* wv   = (const float*)d_in[6];
    const float* bv   = (const float*)d_in[7];
    const float* wd   = (const float*)d_in[8];
    const float* bd   = (const float*)d_in[9];
    const float* lg   = (const float*)d_in[10];
    const float* lb   = (const float*)d_in[11];

    float* out  = (float*)d_out;
    float* attn = out + (size_t)B_ * S_ * D_;  // tuple order: (out, attn)

    const int attn_smem_bytes = ATTN_SMEM_FLOATS * 4;  // 92416 B
    cudaFuncSetAttribute(attn_kernel, cudaFuncAttributeMaxDynamicSharedMemorySize,
                         attn_smem_bytes);

    dim3 pgrid(MTOT / 128, D_ / 128);  // (32, 8)
    qkv_gemm<<<pgrid, 256>>>(q_in, wq, bq, 0);   // g_qx (permuted) + zero g_vcs
    qkv_gemm<<<pgrid, 256>>>(k_in, wk, bk, 1);   // g_kx (permuted)
    qkv_gemm<<<pgrid, 256>>>(k_in, wv, bv, 2);   // g_vx + colsums (v = k)

    attn_kernel<<<dim3(S_ / 64, HB_), 256, attn_smem_bytes>>>(attn);

    attn_norm<<<131072, 256>>>(attn);

    dense_gemm<<<pgrid, 256>>>(wd, bd);          // dense + relu -> g_dense
    ln_kernel<<<MTOT, 256>>>(lg, lb, out);
}

// round 13
// speedup vs baseline: 1.8876x; 1.0323x over previous
#include <cuda_runtime.h>
#include <cstdint>
#include <cstddef>

// Problem constants
#define B_    2
#define S_    2048
#define D_    1024
#define H_    16
#define DK_   64
#define MTOT  4096        // B_*S_
#define HB_   32          // H_*B_

// ---------------------------------------------------------------------------
// Scratch (static device allocations; no dynamic alloc allowed)
// g_qx / g_kx store the dk axis PERMUTED: dk' = (dk&56)|((dk&3)<<1)|((dk>>2)&1)
// (scores invariant; enables paired LDS.64 B-fragment loads in attn).
// g_vx is natural layout (PV + colsum need it).
// ---------------------------------------------------------------------------
static __device__ float g_qx[B_ * H_ * S_ * DK_];   // [b][h][s][dk']
static __device__ float g_kx[B_ * H_ * S_ * DK_];   // [b][h][s][dk']
static __device__ float g_vx[B_ * H_ * S_ * DK_];   // [b][h][s][dk]
static __device__ float g_ctx[(size_t)MTOT * D_];   // [b*S+s][h*64+dk]
static __device__ float g_dense[(size_t)MTOT * D_];
static __device__ float g_rinv[HB_ * S_];           // 1/rowsum per attn row
static __device__ float g_vcs[HB_ * DK_];           // colsum of V per (b*H+h, d)

// ---------------------------------------------------------------------------
// Helpers
// ---------------------------------------------------------------------------
__device__ __forceinline__ float tf32_hi(float x) {
    uint32_t r;
    asm("cvt.rna.tf32.f32 %0, %1;" : "=r"(r) : "f"(x));
    return __uint_as_float(r);
}

__device__ __forceinline__ void mma_tf32(float c[4],
                                         uint32_t a0, uint32_t a1, uint32_t a2, uint32_t a3,
                                         uint32_t b0, uint32_t b1) {
    asm volatile(
        "mma.sync.aligned.m16n8k8.row.col.f32.tf32.tf32.f32 "
        "{%0,%1,%2,%3}, {%4,%5,%6,%7}, {%8,%9}, {%0,%1,%2,%3};\n"
        : "+f"(c[0]), "+f"(c[1]), "+f"(c[2]), "+f"(c[3])
        : "r"(a0), "r"(a1), "r"(a2), "r"(a3), "r"(b0), "r"(b1));
}

__device__ __forceinline__ void cp_async16(uint32_t smem_addr, const void* gptr) {
    asm volatile("cp.async.cg.shared.global [%0], [%1], 16;"
                 :: "r"(smem_addr), "l"(gptr));
}

// ---------------------------------------------------------------------------
// QKV projection GEMM (1xTF32, cp.async double-buffered raw staging).
// mode 0 -> g_qx (permuted dk, also zeroes g_vcs), mode 1 -> g_kx (permuted),
// mode 2 -> g_vx (natural dk, accumulates g_vcs colsums via atomics).
// ---------------------------------------------------------------------------
__global__ __launch_bounds__(256) void qkv_gemm(const float* __restrict__ A,
                                                const float* __restrict__ W,
                                                const float* __restrict__ bias,
                                                int mode) {
    __shared__ float As[2][128 * 20];
    __shared__ float Bs[2][128 * 20];

    const int tid  = threadIdx.x;
    const int lane = tid & 31;
    const int warp = tid >> 5;
    const int wm   = warp & 1;
    const int wn   = warp >> 1;
    const int m0   = blockIdx.x * 128;
    const int n0   = blockIdx.y * 128;

    if (mode == 0 && blockIdx.x == 0 && blockIdx.y == 0) {
#pragma unroll
        for (int i = 0; i < 8; i++) g_vcs[tid + i * 256] = 0.f;
    }

    const int r0 = tid >> 2;
    const int c0 = (tid & 3) * 4;

    float c[4][4][4];
#pragma unroll
    for (int i = 0; i < 4; i++)
#pragma unroll
        for (int j = 0; j < 4; j++)
#pragma unroll
            for (int k = 0; k < 4; k++) c[i][j][k] = 0.f;

    {
        uint32_t as = (uint32_t)__cvta_generic_to_shared(&As[0][0]);
        uint32_t bs = (uint32_t)__cvta_generic_to_shared(&Bs[0][0]);
#pragma unroll
        for (int i = 0; i < 2; i++) {
            int r = r0 + i * 64;
            cp_async16(as + (r * 20 + c0) * 4, A + (size_t)(m0 + r) * 1024 + c0);
            cp_async16(bs + (r * 20 + c0) * 4, W + (size_t)(n0 + r) * 1024 + c0);
        }
        asm volatile("cp.async.commit_group;");
    }

    for (int kt = 0; kt < 64; kt++) {
        asm volatile("cp.async.wait_group 0;");
        __syncthreads();

        if (kt + 1 < 64) {
            int buf = (kt + 1) & 1;
            int k0  = (kt + 1) * 16;
            uint32_t as = (uint32_t)__cvta_generic_to_shared(&As[buf][0]);
            uint32_t bs = (uint32_t)__cvta_generic_to_shared(&Bs[buf][0]);
#pragma unroll
            for (int i = 0; i < 2; i++) {
                int r = r0 + i * 64;
                cp_async16(as + (r * 20 + c0) * 4, A + (size_t)(m0 + r) * 1024 + k0 + c0);
                cp_async16(bs + (r * 20 + c0) * 4, W + (size_t)(n0 + r) * 1024 + k0 + c0);
            }
            asm volatile("cp.async.commit_group;");
        }

        const float* Ab = As[kt & 1];
        const float* Bb = Bs[kt & 1];
#pragma unroll
        for (int kg = 0; kg < 16; kg += 8) {
            uint32_t bh[4][2];
#pragma unroll
            for (int nt = 0; nt < 4; nt++) {
                int boff = (wn * 32 + nt * 8 + (lane >> 2)) * 20 + kg + (lane & 3);
                bh[nt][0] = __float_as_uint(Bb[boff]);
                bh[nt][1] = __float_as_uint(Bb[boff + 4]);
            }
#pragma unroll
            for (int mt = 0; mt < 4; mt++) {
                int aoff = (wm * 64 + mt * 16 + (lane >> 2)) * 20 + kg + (lane & 3);
                uint32_t a0 = __float_as_uint(Ab[aoff]);
                uint32_t a1 = __float_as_uint(Ab[aoff + 8 * 20]);
                uint32_t a2 = __float_as_uint(Ab[aoff + 4]);
                uint32_t a3 = __float_as_uint(Ab[aoff + 8 * 20 + 4]);
#pragma unroll
                for (int nt = 0; nt < 4; nt++)
                    mma_tf32(c[mt][nt], a0, a1, a2, a3, bh[nt][0], bh[nt][1]);
            }
        }
    }

    __syncthreads();

    float csum[4][2];
#pragma unroll
    for (int nt = 0; nt < 4; nt++) { csum[nt][0] = 0.f; csum[nt][1] = 0.f; }

#pragma unroll
    for (int mt = 0; mt < 4; mt++) {
#pragma unroll
        for (int nt = 0; nt < 4; nt++) {
#pragma unroll
            for (int j = 0; j < 4; j++) {
                int row = m0 + wm * 64 + mt * 16 + (lane >> 2) + ((j >> 1) << 3);
                int col = n0 + wn * 32 + nt * 8 + 2 * (lane & 3) + (j & 1);
                float v = c[mt][nt][j] + bias[col];
                int b  = row >> 11;
                int s  = row & 2047;
                int h  = col >> 6;
                int dk = col & 63;
                if (mode == 2) {
                    csum[nt][j & 1] += v;
                    g_vx[(((size_t)(b * H_ + h)) * S_ + s) * DK_ + dk] = v;
                } else {
                    int dkp = (dk & 56) | ((dk & 3) << 1) | ((dk >> 2) & 1);
                    float* dst = (mode == 0) ? g_qx : g_kx;
                    dst[(((size_t)(b * H_ + h)) * S_ + s) * DK_ + dkp] = v;
                }
            }
        }
    }

    if (mode == 2) {
#pragma unroll
        for (int nt = 0; nt < 4; nt++) {
#pragma unroll
            for (int p = 0; p < 2; p++) {
                float v = csum[nt][p];
                v += __shfl_down_sync(0xffffffffu, v, 16);
                v += __shfl_down_sync(0xffffffffu, v, 8);
                v += __shfl_down_sync(0xffffffffu, v, 4);
                if (lane < 4) {
                    int col = n0 + wn * 32 + nt * 8 + 2 * lane + p;
                    int b   = m0 >> 11;
                    int bh  = b * H_ + (col >> 6);
                    atomicAdd(&g_vcs[bh * 64 + (col & 63)], v);
                }
            }
        }
    }
}

// ---------------------------------------------------------------------------
// Dense GEMM (3xTF32 RN via register hi/lo split; cp.async raw staging):
// g_dense = relu(g_ctx @ dense_w^T + dense_b)
// ---------------------------------------------------------------------------
__global__ __launch_bounds__(256) void dense_gemm(const float* __restrict__ W,
                                                  const float* __restrict__ bias) {
    __shared__ float As[2][128 * 20];
    __shared__ float Bs[2][128 * 20];

    const float* Ap = g_ctx;

    const int tid  = threadIdx.x;
    const int lane = tid & 31;
    const int warp = tid >> 5;
    const int wm   = warp & 1;
    const int wn   = warp >> 1;
    const int m0   = blockIdx.x * 128;
    const int n0   = blockIdx.y * 128;

    const int r0 = tid >> 2;
    const int c0 = (tid & 3) * 4;

    float c[4][4][4];
#pragma unroll
    for (int i = 0; i < 4; i++)
#pragma unroll
        for (int j = 0; j < 4; j++)
#pragma unroll
            for (int k = 0; k < 4; k++) c[i][j][k] = 0.f;

    {
        uint32_t as = (uint32_t)__cvta_generic_to_shared(&As[0][0]);
        uint32_t bs = (uint32_t)__cvta_generic_to_shared(&Bs[0][0]);
#pragma unroll
        for (int i = 0; i < 2; i++) {
            int r = r0 + i * 64;
            cp_async16(as + (r * 20 + c0) * 4, Ap + (size_t)(m0 + r) * 1024 + c0);
            cp_async16(bs + (r * 20 + c0) * 4, W + (size_t)(n0 + r) * 1024 + c0);
        }
        asm volatile("cp.async.commit_group;");
    }

    for (int kt = 0; kt < 64; kt++) {
        asm volatile("cp.async.wait_group 0;");
        __syncthreads();

        if (kt + 1 < 64) {
            int buf = (kt + 1) & 1;
            int k0  = (kt + 1) * 16;
            uint32_t as = (uint32_t)__cvta_generic_to_shared(&As[buf][0]);
            uint32_t bs = (uint32_t)__cvta_generic_to_shared(&Bs[buf][0]);
#pragma unroll
            for (int i = 0; i < 2; i++) {
                int r = r0 + i * 64;
                cp_async16(as + (r * 20 + c0) * 4, Ap + (size_t)(m0 + r) * 1024 + k0 + c0);
                cp_async16(bs + (r * 20 + c0) * 4, W + (size_t)(n0 + r) * 1024 + k0 + c0);
            }
            asm volatile("cp.async.commit_group;");
        }

        const float* Ab = As[kt & 1];
        const float* Bb = Bs[kt & 1];
#pragma unroll
        for (int kg = 0; kg < 16; kg += 8) {
            uint32_t bh[4][2], bl[4][2];
#pragma unroll
            for (int nt = 0; nt < 4; nt++) {
                int boff = (wn * 32 + nt * 8 + (lane >> 2)) * 20 + kg + (lane & 3);
                float rb0 = Bb[boff];
                float rb1 = Bb[boff + 4];
                float hb0 = tf32_hi(rb0);
                float hb1 = tf32_hi(rb1);
                bh[nt][0] = __float_as_uint(hb0);
                bh[nt][1] = __float_as_uint(hb1);
                bl[nt][0] = __float_as_uint(rb0 - hb0);
                bl[nt][1] = __float_as_uint(rb1 - hb1);
            }
#pragma unroll
            for (int mt = 0; mt < 4; mt++) {
                int aoff = (wm * 64 + mt * 16 + (lane >> 2)) * 20 + kg + (lane & 3);
                float ra0 = Ab[aoff];
                float ra1 = Ab[aoff + 8 * 20];
                float ra2 = Ab[aoff + 4];
                float ra3 = Ab[aoff + 8 * 20 + 4];
                float ha0 = tf32_hi(ra0), ha1 = tf32_hi(ra1);
                float ha2 = tf32_hi(ra2), ha3 = tf32_hi(ra3);
                uint32_t ah0 = __float_as_uint(ha0), ah1 = __float_as_uint(ha1);
                uint32_t ah2 = __float_as_uint(ha2), ah3 = __float_as_uint(ha3);
                uint32_t al0 = __float_as_uint(ra0 - ha0), al1 = __float_as_uint(ra1 - ha1);
                uint32_t al2 = __float_as_uint(ra2 - ha2), al3 = __float_as_uint(ra3 - ha3);
#pragma unroll
                for (int nt = 0; nt < 4; nt++) {
                    mma_tf32(c[mt][nt], ah0, ah1, ah2, ah3, bh[nt][0], bh[nt][1]);
                    mma_tf32(c[mt][nt], ah0, ah1, ah2, ah3, bl[nt][0], bl[nt][1]);
                    mma_tf32(c[mt][nt], al0, al1, al2, al3, bh[nt][0], bh[nt][1]);
                }
            }
        }
    }

    __syncthreads();
#pragma unroll
    for (int mt = 0; mt < 4; mt++) {
#pragma unroll
        for (int nt = 0; nt < 4; nt++) {
#pragma unroll
            for (int j = 0; j < 4; j++) {
                int row = m0 + wm * 64 + mt * 16 + (lane >> 2) + ((j >> 1) << 3);
                int col = n0 + wn * 32 + nt * 8 + 2 * (lane & 3) + (j & 1);
                float v = c[mt][nt][j] + bias[col];
                g_dense[(size_t)row * 1024 + col] = v > 0.f ? v : 0.f;
            }
        }
    }
}

// ---------------------------------------------------------------------------
// Fused attention kernel (v5: PV via transposed MMA, dp delivered by shuffles;
// no dp smem buffer at all).
// grid = (S/64, H*B), block = 256 (8 warps: wm 0..3 = q-rows, wn 0..1 = k-half)
// Score: Q/K permuted-dk layout, paired LDS.64 B-frags (as v4).
// PV:    O^T = V^T(A, from smem column-reads) @ dp(B, from score regs via shfl).
// ---------------------------------------------------------------------------
#define KSTR 72
#define VSTR 72
#define KVBUF (64 * KSTR + 64 * VSTR)   // 9216 floats per buffer
#define OSTR 66
#define ATTN_SMEM_FLOATS (2 * KVBUF + 64)   // 18496 floats = 73984 B

__global__ __launch_bounds__(256, 2) void attn_kernel(float* __restrict__ attn_out) {
    extern __shared__ float smf[];
    float* rs   = smf + 2 * KVBUF;           // rowsum[64]
    float* Obuf = smf;                       // epilogue alias: 2 x 64 x 66

    const int tid  = threadIdx.x;
    const int lane = tid & 31;
    const int warp = tid >> 5;
    const int wm   = warp & 3;               // q-row group
    const int wn   = warp >> 2;              // k half
    const int g    = lane >> 2;
    const int j    = lane & 3;
    const int hb   = blockIdx.y;             // h*B + b
    const int h    = hb >> 1;
    const int b    = hb & 1;
    const int q0   = blockIdx.x * 64;

    const float* qbase = g_qx + ((size_t)(b * H_ + h)) * S_ * DK_;
    const float* kbase = g_kx + ((size_t)(b * H_ + h)) * S_ * DK_;
    const float* vbase = g_vx + ((size_t)(b * H_ + h)) * S_ * DK_;
    const float invT = 0.03125f;             // 1/sqrt(1024)

    if (tid < 64) rs[tid] = 0.f;

    const int sr  = tid >> 4;                // base row 0..15 (+16 per i)
    const int sc4 = (tid & 15) * 4;          // col 0..60

    // prologue: issue tile 0 loads
    {
        float* Kb = smf;
        float* Vb = smf + 64 * KSTR;
        uint32_t ksm = (uint32_t)__cvta_generic_to_shared(Kb);
        uint32_t vsm = (uint32_t)__cvta_generic_to_shared(Vb);
#pragma unroll
        for (int i = 0; i < 4; i++) {
            int r = sr + i * 16;
            cp_async16(ksm + (r * KSTR + sc4) * 4, kbase + (size_t)r * 64 + sc4);
            cp_async16(vsm + (r * VSTR + sc4) * 4, vbase + (size_t)r * 64 + sc4);
        }
        asm volatile("cp.async.commit_group;");
    }

    // Q fragments in registers (RN tf32, pre-scaled), permuted layout
    uint32_t qa[8][4];
    {
        const float* qr0 = qbase + (size_t)(q0 + wm * 16 + g) * 64;
        const float* qr1 = qr0 + 8 * 64;
#pragma unroll
        for (int kg = 0; kg < 8; kg++) {
            float2 u0 = *(const float2*)(qr0 + kg * 8 + 2 * j);
            float2 u1 = *(const float2*)(qr1 + kg * 8 + 2 * j);
            qa[kg][0] = __float_as_uint(tf32_hi(u0.x * invT));
            qa[kg][2] = __float_as_uint(tf32_hi(u0.y * invT));
            qa[kg][1] = __float_as_uint(tf32_hi(u1.x * invT));
            qa[kg][3] = __float_as_uint(tf32_hi(u1.y * invT));
        }
    }

    // O' accumulators: o[mt][nq][c] -> O'[n = mt*16+g(+8)][q = nq*8+2j(+1)]
    float o[4][2][4];
#pragma unroll
    for (int mt = 0; mt < 4; mt++)
#pragma unroll
        for (int nq = 0; nq < 2; nq++)
#pragma unroll
            for (int k = 0; k < 4; k++) o[mt][nq][k] = 0.f;
    float rs0 = 0.f, rs1 = 0.f;

    const int src0 = 4 * g + (j >> 1);       // shuffle source lanes
    const int src1 = src0 + 2;
    const bool jodd = (j & 1) != 0;

    for (int kt = 0; kt < 32; kt++) {
        float* Kb = smf + (kt & 1) * KVBUF;
        float* Vb = Kb + 64 * KSTR;

        asm volatile("cp.async.wait_group 0;");
        __syncthreads();

        if (kt + 1 < 32) {
            float* Kn = smf + ((kt + 1) & 1) * KVBUF;
            float* Vn = Kn + 64 * KSTR;
            uint32_t ksm = (uint32_t)__cvta_generic_to_shared(Kn);
            uint32_t vsm = (uint32_t)__cvta_generic_to_shared(Vn);
            const float* kb = kbase + (size_t)(kt + 1) * 64 * 64;
            const float* vb = vbase + (size_t)(kt + 1) * 64 * 64;
#pragma unroll
            for (int i = 0; i < 4; i++) {
                int r = sr + i * 16;
                cp_async16(ksm + (r * KSTR + sc4) * 4, kb + (size_t)r * 64 + sc4);
                cp_async16(vsm + (r * VSTR + sc4) * 4, vb + (size_t)r * 64 + sc4);
            }
            asm volatile("cp.async.commit_group;");
        }

        // scores: paired B-frag loads (permuted K layout)
        float s[4][4];
#pragma unroll
        for (int i = 0; i < 4; i++)
#pragma unroll
            for (int k = 0; k < 4; k++) s[i][k] = 0.f;
#pragma unroll
        for (int kg = 0; kg < 8; kg++) {
#pragma unroll
            for (int nt = 0; nt < 4; nt++) {
                int boff = (wn * 32 + nt * 8 + g) * KSTR + kg * 8 + 2 * j;
                float2 kb2 = *(const float2*)(Kb + boff);
                mma_tf32(s[nt], qa[kg][0], qa[kg][1], qa[kg][2], qa[kg][3],
                         __float_as_uint(kb2.x), __float_as_uint(kb2.y));
            }
        }

        // exp -> gmem attn (unnormalized), rowsum regs; dp overwrites s[][]
        const int k0 = kt * 64;
        float* ab = attn_out + ((size_t)hb * S_ + q0 + wm * 16 + g) * S_ + k0 + wn * 32;
#pragma unroll
        for (int nt = 0; nt < 4; nt++) {
            float p0 = __expf(s[nt][0]);
            float p1 = __expf(s[nt][1]);
            float p2 = __expf(s[nt][2]);
            float p3 = __expf(s[nt][3]);
            rs0 += p0 + p1;
            rs1 += p2 + p3;
            *(float2*)(ab + nt * 8 + 2 * j) = make_float2(p0, p1);
            *(float2*)(ab + (size_t)8 * S_ + nt * 8 + 2 * j) = make_float2(p2, p3);
            s[nt][0] = p0 - 1.f;
            s[nt][1] = p1 - 1.f;
            s[nt][2] = p2 - 1.f;
            s[nt][3] = p3 - 1.f;
        }

        // PV (transposed): O'[n][q] += V'[n][k] * dp'[k][q]
        // A-frags = V columns from smem; B-frags = dp from score regs via shfl.
#pragma unroll
        for (int kp = 0; kp < 4; kp++) {
            uint32_t av[4][4];
#pragma unroll
            for (int mt = 0; mt < 4; mt++) {
                int aoff = (wn * 32 + kp * 8 + j) * VSTR + mt * 16 + g;
                av[mt][0] = __float_as_uint(Vb[aoff]);
                av[mt][1] = __float_as_uint(Vb[aoff + 8]);
                av[mt][2] = __float_as_uint(Vb[aoff + 4 * VSTR]);
                av[mt][3] = __float_as_uint(Vb[aoff + 4 * VSTR + 8]);
            }
#pragma unroll
            for (int nq = 0; nq < 2; nq++) {
                float v00 = __shfl_sync(0xffffffffu, s[kp][2 * nq + 0], src0);
                float v01 = __shfl_sync(0xffffffffu, s[kp][2 * nq + 1], src0);
                float v10 = __shfl_sync(0xffffffffu, s[kp][2 * nq + 0], src1);
                float v11 = __shfl_sync(0xffffffffu, s[kp][2 * nq + 1], src1);
                uint32_t b0 = __float_as_uint(jodd ? v01 : v00);
                uint32_t b1 = __float_as_uint(jodd ? v11 : v10);
#pragma unroll
                for (int mt = 0; mt < 4; mt++)
                    mma_tf32(o[mt][nq], av[mt][0], av[mt][1], av[mt][2], av[mt][3],
                             b0, b1);
            }
        }
    }

    // --- epilogue ---
    __syncthreads();   // all PV reads of the KV buffers complete before aliasing
    {
        float* Ob = Obuf + wn * 64 * OSTR;
#pragma unroll
        for (int mt = 0; mt < 4; mt++) {
#pragma unroll
            for (int nq = 0; nq < 2; nq++) {
                int qb = wm * 16 + nq * 8 + 2 * j;
                int nb = mt * 16 + g;
                Ob[qb * OSTR + nb]           = o[mt][nq][0];
                Ob[(qb + 1) * OSTR + nb]     = o[mt][nq][1];
                Ob[qb * OSTR + nb + 8]       = o[mt][nq][2];
                Ob[(qb + 1) * OSTR + nb + 8] = o[mt][nq][3];
            }
        }
    }
    rs0 += __shfl_xor_sync(0xffffffffu, rs0, 1);
    rs0 += __shfl_xor_sync(0xffffffffu, rs0, 2);
    rs1 += __shfl_xor_sync(0xffffffffu, rs1, 1);
    rs1 += __shfl_xor_sync(0xffffffffu, rs1, 2);
    if (j == 0) {
        atomicAdd(&rs[wm * 16 + g], rs0);
        atomicAdd(&rs[wm * 16 + 8 + g], rs1);
    }
    __syncthreads();
    if (tid < 64) {
        float inv = 1.0f / rs[tid];
        g_rinv[(size_t)hb * S_ + q0 + tid] = inv;
        rs[tid] = inv;
    }
    __syncthreads();

    const float* vc = g_vcs + (b * H_ + h) * 64;
#pragma unroll
    for (int i = 0; i < 16; i++) {
        int lin = tid + i * 256;
        int qr  = lin >> 6;
        int d   = lin & 63;
        float val = (Obuf[qr * OSTR + d] + Obuf[64 * OSTR + qr * OSTR + d] + vc[d]) * rs[qr];
        g_ctx[((size_t)(b * S_ + q0 + qr)) * D_ + h * 64 + d] = val;
    }
}

// ---------------------------------------------------------------------------
// Normalize attn in place: attn[hb][q][k] *= g_rinv[hb*S+q]
// ---------------------------------------------------------------------------
__global__ __launch_bounds__(256) void attn_norm(float* __restrict__ attn) {
    size_t i = (size_t)blockIdx.x * 256 + threadIdx.x;  // float4 index
    float inv = g_rinv[i >> 9];                          // 512 float4 per row
    float4* p = (float4*)attn;
    float4 v = p[i];
    v.x *= inv; v.y *= inv; v.z *= inv; v.w *= inv;
    p[i] = v;
}

// ---------------------------------------------------------------------------
// LayerNorm over rows of g_dense -> out
// ---------------------------------------------------------------------------
__global__ __launch_bounds__(256) void ln_kernel(const float* __restrict__ lg,
                                                 const float* __restrict__ lb,
                                                 float* __restrict__ out) {
    const int row = blockIdx.x;
    const int tid = threadIdx.x;
    const float* x = g_dense + (size_t)row * 1024;
    float4 xv = *(const float4*)(x + tid * 4);
    float s  = xv.x + xv.y + xv.z + xv.w;
    float ss = fmaf(xv.x, xv.x, fmaf(xv.y, xv.y, fmaf(xv.z, xv.z, xv.w * xv.w)));
#pragma unroll
    for (int off = 16; off > 0; off >>= 1) {
        s  += __shfl_xor_sync(0xffffffffu, s, off);
        ss += __shfl_xor_sync(0xffffffffu, ss, off);
    }
    __shared__ float sm1[8], sm2[8];
    if ((tid & 31) == 0) { sm1[tid >> 5] = s; sm2[tid >> 5] = ss; }
    __syncthreads();
    if (tid < 32) {
        float a  = (tid < 8) ? sm1[tid] : 0.f;
        float b2 = (tid < 8) ? sm2[tid] : 0.f;
#pragma unroll
        for (int off = 4; off > 0; off >>= 1) {
            a  += __shfl_xor_sync(0xffffffffu, a, off);
            b2 += __shfl_xor_sync(0xffffffffu, b2, off);
        }
        if (tid == 0) { sm1[0] = a; sm2[0] = b2; }
    }
    __syncthreads();
    float mean = sm1[0] * (1.0f / 1024.0f);
    float var  = sm2[0] * (1.0f / 1024.0f) - mean * mean;
    float rstd = rsqrtf(var + 1e-5f);
    float4 gv = *(const float4*)(lg + tid * 4);
    float4 bv = *(const float4*)(lb + tid * 4);
    float4 ov;
    ov.x = (xv.x - mean) * rstd * gv.x + bv.x;
    ov.y = (xv.y - mean) * rstd * gv.y + bv.y;
    ov.z = (xv.z - mean) * rstd * gv.z + bv.z;
    ov.w = (xv.w - mean) * rstd * gv.w + bv.w;
    *(float4*)(out + (size_t)row * 1024 + tid * 4) = ov;
}

// ---------------------------------------------------------------------------
// Launch (7 launches; attn is #4 so the harness ncu capture samples it)
// ---------------------------------------------------------------------------
extern "C" void kernel_launch(void* const* d_in, const int* in_sizes, int n_in,
                              void* d_out, int out_size) {
    const float* k_in = (const float*)d_in[0];
    const float* q_in = (const float*)d_in[1];
    const float* wk   = (const float*)d_in[2];
    const float* bk   = (const float*)d_in[3];
    const float* wq   = (const float*)d_in[4];
    const float* bq   = (const float*)d_in[5];
    const float* wv   = (const float*)d_in[6];
    const float* bv   = (const float*)d_in[7];
    const float* wd   = (const float*)d_in[8];
    const float* bd   = (const float*)d_in[9];
    const float* lg   = (const float*)d_in[10];
    const float* lb   = (const float*)d_in[11];

    float* out  = (float*)d_out;
    float* attn = out + (size_t)B_ * S_ * D_;  // tuple order: (out, attn)

    const int attn_smem_bytes = ATTN_SMEM_FLOATS * 4;  // 73984 B
    cudaFuncSetAttribute(attn_kernel, cudaFuncAttributeMaxDynamicSharedMemorySize,
                         attn_smem_bytes);

    dim3 pgrid(MTOT / 128, D_ / 128);  // (32, 8)
    qkv_gemm<<<pgrid, 256>>>(q_in, wq, bq, 0);   // g_qx (permuted) + zero g_vcs
    qkv_gemm<<<pgrid, 256>>>(k_in, wk, bk, 1);   // g_kx (permuted)
    qkv_gemm<<<pgrid, 256>>>(k_in, wv, bv, 2);   // g_vx + colsums (v = k)

    attn_kernel<<<dim3(S_ / 64, HB_), 256, attn_smem_bytes>>>(attn);

    attn_norm<<<131072, 256>>>(attn);

    dense_gemm<<<pgrid, 256>>>(wd, bd);          // dense + relu -> g_dense
    ln_kernel<<<MTOT, 256>>>(lg, lb, out);
}